// round 11
// baseline (speedup 1.0000x reference)
#include <cuda_runtime.h>
#include <cuda_bf16.h>
#include <math.h>
#include <stdint.h>

// ---------------- problem constants ----------------
#define BSZ   32
#define HH    56
#define WW_   56
#define CC    192
#define LL    (HH*WW_)          // 3136
#define WS    7
#define NN    49
#define NHH   6
#define HD    32
#define SHIFT 3
#define NWIN  64
#define BW    (BSZ*NWIN)        // 2048
#define TOK   (BW*NN)           // 100352
#define HID   768

typedef __nv_bfloat16 bf16;

// ---------------- scratch (static device, no allocs) ----------------
__device__ __align__(256) bf16 g_ln1 [(size_t)TOK*CC];
__device__ __align__(256) bf16 g_qkvb[(size_t)TOK*3*CC];
__device__ __align__(256) bf16 g_attnb[(size_t)TOK*CC];
__device__ __align__(256) bf16 g_ln2 [(size_t)TOK*CC];
__device__ __align__(256) bf16 g_h1b [(size_t)TOK*HID];
__device__ __align__(256) float g_x1 [(size_t)TOK*CC];
__device__ __align__(256) bf16 g_wq[3*CC*CC];
__device__ __align__(256) bf16 g_wp[CC*CC];
__device__ __align__(256) bf16 g_w1[HID*CC];
__device__ __align__(256) bf16 g_w2[CC*HID];
__device__ __align__(256) float g_bias[4*NHH*64*64];   // precomputed bias+mask tables

// ---------------- helpers ----------------
__device__ __forceinline__ float warpSum(float v){
    #pragma unroll
    for (int o=16;o;o>>=1) v += __shfl_xor_sync(0xffffffffu, v, o);
    return v;
}
__device__ __forceinline__ void mma_bf16(float* acc, uint32_t a0, uint32_t a1, uint32_t a2, uint32_t a3,
                                         uint32_t b0, uint32_t b1){
    asm volatile(
        "mma.sync.aligned.m16n8k16.row.col.f32.bf16.bf16.f32 "
        "{%0,%1,%2,%3}, {%4,%5,%6,%7}, {%8,%9}, {%0,%1,%2,%3};"
        : "+f"(acc[0]), "+f"(acc[1]), "+f"(acc[2]), "+f"(acc[3])
        : "r"(a0), "r"(a1), "r"(a2), "r"(a3), "r"(b0), "r"(b1));
}
__device__ __forceinline__ void ldm4(uint32_t* r, const void* p){
    uint32_t a = (uint32_t)__cvta_generic_to_shared(p);
    asm volatile("ldmatrix.sync.aligned.m8n8.x4.shared.b16 {%0,%1,%2,%3}, [%4];"
                 : "=r"(r[0]), "=r"(r[1]), "=r"(r[2]), "=r"(r[3]) : "r"(a));
}
__device__ __forceinline__ void cpa16(void* dst, const void* src){
    uint32_t d = (uint32_t)__cvta_generic_to_shared(dst);
    asm volatile("cp.async.cg.shared.global [%0], [%1], 16;" :: "r"(d), "l"(src));
}
__device__ __forceinline__ uint32_t packbf2(float a, float b){
    __nv_bfloat162 p = __floats2bfloat162_rn(a, b);
    return *(uint32_t*)&p;
}

static __device__ __forceinline__ size_t winrow_to_img(int m){
    int win = m / NN, n = m % NN;
    int b = win >> 6, wi = win & 63;
    int hr = (wi >> 3)*WS + n/WS;
    int wr = (wi & 7)*WS + n%WS;
    int h = hr + SHIFT; if (h >= HH) h -= HH;
    int w = wr + SHIFT; if (w >= WW_) w -= WW_;
    return (size_t)b*LL + (size_t)h*WW_ + w;
}

// ---------------- fused fp32 -> bf16 weight convert ----------------
#define S0 (3*CC*CC)
#define S1 (S0 + CC*CC)
#define S2 (S1 + HID*CC)
#define S3 (S2 + CC*HID)
__global__ void f2bf4_kernel(const float* __restrict__ a, const float* __restrict__ b,
                             const float* __restrict__ c, const float* __restrict__ d,
                             bf16* __restrict__ oa, bf16* __restrict__ ob,
                             bf16* __restrict__ oc, bf16* __restrict__ od){
    int i = blockIdx.x*256 + threadIdx.x;
    if (i < S0)      oa[i]      = __float2bfloat16(a[i]);
    else if (i < S1) ob[i - S0] = __float2bfloat16(b[i - S0]);
    else if (i < S2) oc[i - S1] = __float2bfloat16(c[i - S1]);
    else if (i < S3) od[i - S2] = __float2bfloat16(d[i - S2]);
}

// ---------------- bias table precompute ----------------
__global__ __launch_bounds__(256) void bias_pre_kernel(const float* __restrict__ rpb,
                                                       float* __restrict__ bt)
{
    int wtype = blockIdx.x / NHH;
    int head  = blockIdx.x % NHH;
    int whE = wtype >> 1, wwE = wtype & 1;
    float* o = bt + (size_t)blockIdx.x * 4096;
    for (int idx = threadIdx.x; idx < 4096; idx += 256) {
        int r = idx >> 6, c = idx & 63;
        float v;
        if (c >= NN) v = -1e9f;
        else if (r >= NN) v = 0.f;
        else {
            int ih = r / WS, iw = r % WS;
            int jh = c / WS, jw = c % WS;
            int grh = whE ? ((ih < 4) ? 1 : 2) : 0;
            int grw = wwE ? ((iw < 4) ? 1 : 2) : 0;
            int gch = whE ? ((jh < 4) ? 1 : 2) : 0;
            int gcw = wwE ? ((jw < 4) ? 1 : 2) : 0;
            v = rpb[((ih-jh+6)*13 + (iw-jw+6))*NHH + head]
              + (((grh*3+grw) != (gch*3+gcw)) ? -100.f : 0.f);
        }
        o[idx] = v;
    }
}

// ---------------- LayerNorm: warp per row, single pass ----------------
template<bool GATHER>
__global__ __launch_bounds__(256) void ln_kernel(const float* __restrict__ x,
                                                 const float* __restrict__ gamma,
                                                 const float* __restrict__ beta,
                                                 bf16* __restrict__ out)
{
    int w = threadIdx.x >> 5, lane = threadIdx.x & 31;
    int t = blockIdx.x*8 + w;
    size_t src = GATHER ? winrow_to_img(t) * CC : (size_t)t * CC;
    float v[6];
    #pragma unroll
    for (int i = 0; i < 6; i++) v[i] = x[src + lane + i*32];
    float s = 0.f, q = 0.f;
    #pragma unroll
    for (int i = 0; i < 6; i++) { s += v[i]; q = fmaf(v[i], v[i], q); }
    s = warpSum(s); q = warpSum(q);
    float mean = s * (1.f/CC);
    float rstd = rsqrtf(q * (1.f/CC) - mean*mean + 1e-5f);
    size_t dst = (size_t)t * CC;
    #pragma unroll
    for (int i = 0; i < 6; i++) {
        int ch = lane + i*32;
        out[dst + ch] = __float2bfloat16((v[i] - mean) * rstd * __ldg(gamma+ch) + __ldg(beta+ch));
    }
}

// ================= shared epilogue =================
// EPI 0: +bias -> bf16 | 1: +bias,gelu -> bf16 | 2: +bias +x[imgrow] -> fp32 | 3: +bias +xin -> fp32
template<int EPI, int N>
__device__ __forceinline__ void gemm_epilogue(float acc[2][6][4], int mBase, int nBase,
                                              int wm, int wn, int g, int t4,
                                              const float* bias, const float* xin, void* outp)
{
    #pragma unroll
    for (int ni = 0; ni < 6; ni++) {
        int n = nBase + wn + ni*8 + t4*2;
        float b0v = __ldg(bias + n), b1v = __ldg(bias + n + 1);
        #pragma unroll
        for (int mi = 0; mi < 2; mi++) {
            #pragma unroll
            for (int h = 0; h < 2; h++) {
                int m = mBase + wm + mi*16 + h*8 + g;
                float u0 = acc[mi][ni][h*2+0] + b0v;
                float u1 = acc[mi][ni][h*2+1] + b1v;
                if (EPI == 1) {
                    float y0 = 0.7978845608028654f * (u0 + 0.044715f*u0*u0*u0);
                    float y1 = 0.7978845608028654f * (u1 + 0.044715f*u1*u1*u1);
                    float t0 = 1.f - 2.f/(__expf(2.f*y0)+1.f);
                    float t1 = 1.f - 2.f/(__expf(2.f*y1)+1.f);
                    u0 = 0.5f*u0*(1.f+t0);
                    u1 = 0.5f*u1*(1.f+t1);
                }
                if (EPI == 0 || EPI == 1) {
                    *(uint32_t*)((bf16*)outp + (size_t)m * N + n) = packbf2(u0, u1);
                } else {
                    size_t drow = (EPI == 2) ? winrow_to_img(m) : (size_t)m;
                    size_t o = drow * CC + n;
                    float2 xv = *(const float2*)(xin + o);
                    float2 ov; ov.x = u0 + xv.x; ov.y = u1 + xv.y;
                    *(float2*)((float*)outp + o) = ov;
                }
            }
        }
    }
}

// ================= full-K GEMM for K=192: one load phase, one barrier =================
// tile 128(M) x 96(N) x 192(K). smem: A 128x200, B 96x200 bf16 = 89.6KB.
#define FLDA 200
#define FK_SMEM ((128*FLDA + 96*FLDA)*2)    // 89600 bytes

template<int EPI, int N>
__global__ __launch_bounds__(256) void gemm_fullk(const bf16* __restrict__ A,
                                                  const bf16* __restrict__ Wt,
                                                  const float* __restrict__ bias,
                                                  const float* __restrict__ xin,
                                                  void* __restrict__ outp)
{
    extern __shared__ __align__(16) bf16 smem[];
    bf16* As = smem;               // 128 x FLDA
    bf16* Bs = smem + 128*FLDA;    // 96 x FLDA

    int tid = threadIdx.x;
    int wid = tid >> 5, lane = tid & 31;
    int g = lane >> 2, t4 = lane & 3;
    int wm = (wid >> 1) * 32;
    int wn = (wid & 1) * 48;
    int mBase = blockIdx.y * 128;
    int nBase = blockIdx.x * 96;

    const bf16* Abase = A  + (size_t)mBase * CC;
    const bf16* Bbase = Wt + (size_t)nBase * CC;

    // A: 128 rows x 24 chunks of 16B = 3072 chunks, 12/thread
    #pragma unroll
    for (int i = 0; i < 12; i++) {
        int idx = tid + i*256;
        int r = idx / 24, c = idx % 24;
        cpa16(&As[r*FLDA + c*8], Abase + (size_t)r*CC + c*8);
    }
    // B: 96 rows x 24 chunks = 2304 chunks, 9/thread
    #pragma unroll
    for (int i = 0; i < 9; i++) {
        int idx = tid + i*256;
        int r = idx / 24, c = idx % 24;
        cpa16(&Bs[r*FLDA + c*8], Bbase + (size_t)r*CC + c*8);
    }
    asm volatile("cp.async.commit_group;" ::: "memory");
    asm volatile("cp.async.wait_group 0;" ::: "memory");
    __syncthreads();

    float acc[2][6][4];
    #pragma unroll
    for (int mi=0;mi<2;mi++)
        #pragma unroll
        for (int ni=0;ni<6;ni++)
            #pragma unroll
            for (int c=0;c<4;c++) acc[mi][ni][c] = 0.f;

    int aRowOff = ((lane>>3)&1)*8 + (lane&7);
    int aColOff = ((lane>>4)&1)*8;
    int bRowOff = ((lane>>4)&1)*8 + (lane&7);
    int bColOff = ((lane>>3)&1)*8;

    #pragma unroll
    for (int ks = 0; ks < 12; ks++) {
        uint32_t af[2][4], bfr[3][4];
        #pragma unroll
        for (int mi = 0; mi < 2; mi++)
            ldm4(af[mi], &As[(wm + mi*16 + aRowOff)*FLDA + ks*16 + aColOff]);
        #pragma unroll
        for (int p = 0; p < 3; p++)
            ldm4(bfr[p], &Bs[(wn + p*16 + bRowOff)*FLDA + ks*16 + bColOff]);
        #pragma unroll
        for (int mi = 0; mi < 2; mi++)
            #pragma unroll
            for (int p = 0; p < 3; p++) {
                mma_bf16(acc[mi][2*p  ], af[mi][0], af[mi][1], af[mi][2], af[mi][3],
                         bfr[p][0], bfr[p][1]);
                mma_bf16(acc[mi][2*p+1], af[mi][0], af[mi][1], af[mi][2], af[mi][3],
                         bfr[p][2], bfr[p][3]);
            }
    }

    gemm_epilogue<EPI, N>(acc, mBase, nBase, wm, wn, g, t4, bias, xin, outp);
}

// ================= pipelined GEMM (for fc2, K=768) =================
#define LDA 40
#define GEMM_SMEM ((3*128*LDA + 3*96*LDA)*2)   // 53760 bytes

template<int EPI, int N, int K>
__global__ __launch_bounds__(256) void mma_gemm(const bf16* __restrict__ A,
                                                const bf16* __restrict__ Wt,
                                                const float* __restrict__ bias,
                                                const float* __restrict__ xin,
                                                void* __restrict__ outp)
{
    constexpr int NITER = K / 32;
    extern __shared__ __align__(16) bf16 smem[];
    bf16* AsB = smem;
    bf16* BsB = smem + 3*128*LDA;

    int tid = threadIdx.x;
    int wid = tid >> 5, lane = tid & 31;
    int g = lane >> 2, t4 = lane & 3;
    int wm = (wid >> 1) * 32;
    int wn = (wid & 1) * 48;
    int mBase = blockIdx.y * 128;
    int nBase = blockIdx.x * 96;

    const bf16* Abase = A  + (size_t)mBase * K;
    const bf16* Bbase = Wt + (size_t)nBase * K;

    int lrA  = tid >> 2;
    int lc8A = tid & 3;
    int lrB  = tid >> 1;
    int lc8B = (tid & 1) * 2;

    auto loadTiles = [&](int kt, int s){
        bf16* as = AsB + s*128*LDA;
        bf16* bs = BsB + s*96*LDA;
        #pragma unroll
        for (int i = 0; i < 2; i++) {
            int r = lrA + i*64;
            cpa16(&as[r*LDA + lc8A*8], Abase + (size_t)r*K + kt + lc8A*8);
        }
        if (tid < 192) {
            cpa16(&bs[lrB*LDA + lc8B*8],     Bbase + (size_t)lrB*K + kt + lc8B*8);
            cpa16(&bs[lrB*LDA + lc8B*8 + 8], Bbase + (size_t)lrB*K + kt + lc8B*8 + 8);
        }
        asm volatile("cp.async.commit_group;" ::: "memory");
    };

    float acc[2][6][4];
    #pragma unroll
    for (int mi=0;mi<2;mi++)
        #pragma unroll
        for (int ni=0;ni<6;ni++)
            #pragma unroll
            for (int c=0;c<4;c++) acc[mi][ni][c] = 0.f;

    int aRowOff = ((lane>>3)&1)*8 + (lane&7);
    int aColOff = ((lane>>4)&1)*8;
    int bRowOff = ((lane>>4)&1)*8 + (lane&7);
    int bColOff = ((lane>>3)&1)*8;

    loadTiles(0, 0);
    loadTiles(32, 1);

    #pragma unroll
    for (int it = 0; it < NITER; it++) {
        if (it + 1 < NITER) asm volatile("cp.async.wait_group 1;" ::: "memory");
        else                asm volatile("cp.async.wait_group 0;" ::: "memory");
        __syncthreads();
        if (it + 2 < NITER) loadTiles((it+2)*32, (it+2)%3);

        const bf16* as = AsB + (it%3)*128*LDA;
        const bf16* bs = BsB + (it%3)*96*LDA;
        #pragma unroll
        for (int ks = 0; ks < 2; ks++) {
            uint32_t af[2][4], bfr[3][4];
            #pragma unroll
            for (int mi = 0; mi < 2; mi++)
                ldm4(af[mi], &as[(wm + mi*16 + aRowOff)*LDA + ks*16 + aColOff]);
            #pragma unroll
            for (int p = 0; p < 3; p++)
                ldm4(bfr[p], &bs[(wn + p*16 + bRowOff)*LDA + ks*16 + bColOff]);
            #pragma unroll
            for (int mi = 0; mi < 2; mi++)
                #pragma unroll
                for (int p = 0; p < 3; p++) {
                    mma_bf16(acc[mi][2*p  ], af[mi][0], af[mi][1], af[mi][2], af[mi][3],
                             bfr[p][0], bfr[p][1]);
                    mma_bf16(acc[mi][2*p+1], af[mi][0], af[mi][1], af[mi][2], af[mi][3],
                             bfr[p][2], bfr[p][3]);
                }
        }
        __syncthreads();
    }

    gemm_epilogue<EPI, N>(acc, mBase, nBase, wm, wn, g, t4, bias, xin, outp);
}

// ---------------- HMMA windowed attention: one block per (window, head) ----------------
#define ALD 40
#define VLD 72

__global__ __launch_bounds__(128) void attn_mma(const bf16* __restrict__ qkv,
                                                const float* __restrict__ btab,
                                                bf16* __restrict__ out)
{
    __shared__ __align__(16) bf16 sq[64*ALD];
    __shared__ __align__(16) bf16 sk[64*ALD];
    __shared__ __align__(16) bf16 sVt[32*VLD];
    __shared__ __align__(16) float sbias[64*64];

    int win  = blockIdx.x / NHH;
    int head = blockIdx.x % NHH;
    int tid  = threadIdx.x;
    int lane = tid & 31, w = tid >> 5;
    int g = lane >> 2, t4 = lane & 3;

    int wi = win & 63;
    int wtype = (((wi>>3) == 7) ? 2 : 0) + (((wi&7) == 7) ? 1 : 0);
    const float* bt = btab + ((size_t)(wtype*NHH + head))*4096;
    #pragma unroll
    for (int i = 0; i < 8; i++)
        cpa16(&sbias[(tid + i*128)*4], bt + (tid + i*128)*4);
    asm volatile("cp.async.commit_group;" ::: "memory");

    uint32_t* zq = (uint32_t*)sq;
    uint32_t* zk = (uint32_t*)sk;
    uint32_t* zv = (uint32_t*)sVt;
    #pragma unroll
    for (int i = 0; i < 10; i++) { zq[tid + i*128] = 0u; zk[tid + i*128] = 0u; }
    #pragma unroll
    for (int i = 0; i < 9; i++)  { zv[tid + i*128] = 0u; }
    __syncthreads();

    const bf16* base = qkv + (size_t)win*NN*(3*CC) + head*HD;
    const float scale = 0.17677669529663687f;
    for (int i = tid; i < NN*HD; i += 128) {
        int n = i >> 5, d = i & 31;
        float qv = __bfloat162float(base[(size_t)n*(3*CC) + d]) * scale;
        sq[n*ALD + d]  = __float2bfloat16(qv);
        sk[n*ALD + d]  = base[(size_t)n*(3*CC) + CC + d];
        sVt[d*VLD + n] = base[(size_t)n*(3*CC) + 2*CC + d];
    }
    asm volatile("cp.async.wait_group 0;" ::: "memory");
    __syncthreads();

    float sa[8][4];
    #pragma unroll
    for (int nt = 0; nt < 8; nt++)
        #pragma unroll
        for (int c = 0; c < 4; c++) sa[nt][c] = 0.f;

    int r0 = w*16 + g;
    #pragma unroll
    for (int kt = 0; kt < 2; kt++) {
        uint32_t a0 = *(const uint32_t*)&sq[(r0  )*ALD + kt*16 + t4*2    ];
        uint32_t a1 = *(const uint32_t*)&sq[(r0+8)*ALD + kt*16 + t4*2    ];
        uint32_t a2 = *(const uint32_t*)&sq[(r0  )*ALD + kt*16 + t4*2 + 8];
        uint32_t a3 = *(const uint32_t*)&sq[(r0+8)*ALD + kt*16 + t4*2 + 8];
        #pragma unroll
        for (int nt = 0; nt < 8; nt++) {
            int n0 = nt*8 + g;
            uint32_t b0 = *(const uint32_t*)&sk[n0*ALD + kt*16 + t4*2    ];
            uint32_t b1 = *(const uint32_t*)&sk[n0*ALD + kt*16 + t4*2 + 8];
            mma_bf16(sa[nt], a0, a1, a2, a3, b0, b1);
        }
    }

    int rlo = r0, rhi = r0 + 8;
    float mlo = -1e30f, mhi = -1e30f;
    #pragma unroll
    for (int nt = 0; nt < 8; nt++) {
        float2 blo = *(const float2*)&sbias[rlo*64 + nt*8 + t4*2];
        float2 bhi = *(const float2*)&sbias[rhi*64 + nt*8 + t4*2];
        sa[nt][0] += blo.x; sa[nt][1] += blo.y;
        sa[nt][2] += bhi.x; sa[nt][3] += bhi.y;
        mlo = fmaxf(mlo, fmaxf(sa[nt][0], sa[nt][1]));
        mhi = fmaxf(mhi, fmaxf(sa[nt][2], sa[nt][3]));
    }
    mlo = fmaxf(mlo, __shfl_xor_sync(0xffffffffu, mlo, 1));
    mlo = fmaxf(mlo, __shfl_xor_sync(0xffffffffu, mlo, 2));
    mhi = fmaxf(mhi, __shfl_xor_sync(0xffffffffu, mhi, 1));
    mhi = fmaxf(mhi, __shfl_xor_sync(0xffffffffu, mhi, 2));
    float slo = 0.f, shi = 0.f;
    #pragma unroll
    for (int nt = 0; nt < 8; nt++) {
        sa[nt][0] = __expf(sa[nt][0] - mlo);
        sa[nt][1] = __expf(sa[nt][1] - mlo);
        sa[nt][2] = __expf(sa[nt][2] - mhi);
        sa[nt][3] = __expf(sa[nt][3] - mhi);
        slo += sa[nt][0] + sa[nt][1];
        shi += sa[nt][2] + sa[nt][3];
    }
    slo += __shfl_xor_sync(0xffffffffu, slo, 1);
    slo += __shfl_xor_sync(0xffffffffu, slo, 2);
    shi += __shfl_xor_sync(0xffffffffu, shi, 1);
    shi += __shfl_xor_sync(0xffffffffu, shi, 2);
    float ilo = 1.f / slo, ihi = 1.f / shi;

    uint32_t plo[8], phi[8];
    #pragma unroll
    for (int nt = 0; nt < 8; nt++) {
        plo[nt] = packbf2(sa[nt][0]*ilo, sa[nt][1]*ilo);
        phi[nt] = packbf2(sa[nt][2]*ihi, sa[nt][3]*ihi);
    }

    float oacc[4][4];
    #pragma unroll
    for (int nt = 0; nt < 4; nt++)
        #pragma unroll
        for (int c = 0; c < 4; c++) oacc[nt][c] = 0.f;

    #pragma unroll
    for (int kt = 0; kt < 4; kt++) {
        uint32_t a0 = plo[2*kt], a1 = phi[2*kt], a2 = plo[2*kt+1], a3 = phi[2*kt+1];
        #pragma unroll
        for (int nt = 0; nt < 4; nt++) {
            int n0 = nt*8 + g;
            uint32_t b0 = *(const uint32_t*)&sVt[n0*VLD + kt*16 + t4*2    ];
            uint32_t b1 = *(const uint32_t*)&sVt[n0*VLD + kt*16 + t4*2 + 8];
            mma_bf16(oacc[nt], a0, a1, a2, a3, b0, b1);
        }
    }

    #pragma unroll
    for (int nt = 0; nt < 4; nt++) {
        int col = nt*8 + t4*2;
        if (rlo < NN)
            *(uint32_t*)(out + ((size_t)(win*NN + rlo))*CC + head*HD + col) =
                packbf2(oacc[nt][0], oacc[nt][1]);
        if (rhi < NN)
            *(uint32_t*)(out + ((size_t)(win*NN + rhi))*CC + head*HD + col) =
                packbf2(oacc[nt][2], oacc[nt][3]);
    }
}

// ---------------- launch ----------------
extern "C" void kernel_launch(void* const* d_in, const int* in_sizes, int n_in,
                              void* d_out, int out_size)
{
    const float* x      = (const float*)d_in[0];
    const float* qkv_w  = (const float*)d_in[1];
    const float* qkv_b  = (const float*)d_in[2];
    const float* proj_w = (const float*)d_in[3];
    const float* proj_b = (const float*)d_in[4];
    const float* rpb    = (const float*)d_in[5];
    const float* n1g    = (const float*)d_in[6];
    const float* n1b    = (const float*)d_in[7];
    const float* n2g    = (const float*)d_in[8];
    const float* n2b    = (const float*)d_in[9];
    const float* w1     = (const float*)d_in[10];
    const float* b1     = (const float*)d_in[11];
    const float* w2     = (const float*)d_in[12];
    const float* b2     = (const float*)d_in[13];
    float* out = (float*)d_out;

    bf16 *p_ln1, *p_qkvb, *p_attnb, *p_ln2, *p_h1b, *p_wq, *p_wp, *p_w1, *p_w2;
    float *p_x1, *p_bias;
    cudaGetSymbolAddress((void**)&p_ln1,  g_ln1);
    cudaGetSymbolAddress((void**)&p_qkvb, g_qkvb);
    cudaGetSymbolAddress((void**)&p_attnb,g_attnb);
    cudaGetSymbolAddress((void**)&p_ln2,  g_ln2);
    cudaGetSymbolAddress((void**)&p_h1b,  g_h1b);
    cudaGetSymbolAddress((void**)&p_x1,   g_x1);
    cudaGetSymbolAddress((void**)&p_wq,   g_wq);
    cudaGetSymbolAddress((void**)&p_wp,   g_wp);
    cudaGetSymbolAddress((void**)&p_w1,   g_w1);
    cudaGetSymbolAddress((void**)&p_w2,   g_w2);
    cudaGetSymbolAddress((void**)&p_bias, g_bias);

    cudaFuncSetAttribute(gemm_fullk<0, 3*CC>, cudaFuncAttributeMaxDynamicSharedMemorySize, FK_SMEM);
    cudaFuncSetAttribute(gemm_fullk<2, CC>,   cudaFuncAttributeMaxDynamicSharedMemorySize, FK_SMEM);
    cudaFuncSetAttribute(gemm_fullk<1, HID>,  cudaFuncAttributeMaxDynamicSharedMemorySize, FK_SMEM);
    cudaFuncSetAttribute(mma_gemm<3, CC, HID>, cudaFuncAttributeMaxDynamicSharedMemorySize, GEMM_SMEM);

    // 0) weights -> bf16 + bias tables
    f2bf4_kernel<<<(S3 + 255)/256, 256>>>(qkv_w, proj_w, w1, w2, p_wq, p_wp, p_w1, p_w2);
    bias_pre_kernel<<<4*NHH, 256>>>(rpb, p_bias);

    // 1) LN1 + roll + window partition -> bf16
    ln_kernel<true><<<TOK/8, 256>>>(x, n1g, n1b, p_ln1);

    // 2) qkv GEMM (full-K)
    gemm_fullk<0, 3*CC><<<dim3(6, TOK/128), 256, FK_SMEM>>>(p_ln1, p_wq, qkv_b, nullptr, p_qkvb);

    // 3) windowed attention (HMMA)
    attn_mma<<<BW*NHH, 128>>>(p_qkvb, p_bias, p_attnb);

    // 4) proj GEMM (full-K) + window reverse + residual -> g_x1 (fp32)
    gemm_fullk<2, CC><<<dim3(2, TOK/128), 256, FK_SMEM>>>(p_attnb, p_wp, proj_b, x, p_x1);

    // 5) LN2 -> bf16
    ln_kernel<false><<<TOK/8, 256>>>(p_x1, n2g, n2b, p_ln2);

    // 6) fc1 + gelu (full-K) -> bf16
    gemm_fullk<1, HID><<<dim3(8, TOK/128), 256, FK_SMEM>>>(p_ln2, p_w1, b1, nullptr, p_h1b);

    // 7) fc2 + bias + residual (pipelined, K=768) -> d_out (fp32)
    mma_gemm<3, CC, HID><<<dim3(2, TOK/128), 256, GEMM_SMEM>>>(p_h1b, p_w2, b2, p_x1, out);
}

// round 14
// speedup vs baseline: 1.0307x; 1.0307x over previous
#include <cuda_runtime.h>
#include <cuda_bf16.h>
#include <math.h>
#include <stdint.h>

// ---------------- problem constants ----------------
#define BSZ   32
#define HH    56
#define WW_   56
#define CC    192
#define LL    (HH*WW_)          // 3136
#define WS    7
#define NN    49
#define NHH   6
#define HD    32
#define SHIFT 3
#define NWIN  64
#define BW    (BSZ*NWIN)        // 2048
#define TOK   (BW*NN)           // 100352
#define HID   768

typedef __nv_bfloat16 bf16;

// ---------------- scratch (static device, no allocs) ----------------
__device__ __align__(256) bf16 g_ln1 [(size_t)TOK*CC];
__device__ __align__(256) bf16 g_qkvb[(size_t)TOK*3*CC];
__device__ __align__(256) bf16 g_attnb[(size_t)TOK*CC];
__device__ __align__(256) bf16 g_ln2 [(size_t)TOK*CC];
__device__ __align__(256) bf16 g_h1b [(size_t)TOK*HID];
__device__ __align__(256) float g_x1 [(size_t)TOK*CC];
__device__ __align__(256) bf16 g_wq[3*CC*CC];
__device__ __align__(256) bf16 g_wp[CC*CC];
__device__ __align__(256) bf16 g_w1[HID*CC];
__device__ __align__(256) bf16 g_w2[CC*HID];
__device__ __align__(256) float g_bias[4*NHH*64*64];   // precomputed bias+mask tables

// ---------------- helpers ----------------
__device__ __forceinline__ float warpSum(float v){
    #pragma unroll
    for (int o=16;o;o>>=1) v += __shfl_xor_sync(0xffffffffu, v, o);
    return v;
}
__device__ __forceinline__ void mma_bf16(float* acc, uint32_t a0, uint32_t a1, uint32_t a2, uint32_t a3,
                                         uint32_t b0, uint32_t b1){
    asm volatile(
        "mma.sync.aligned.m16n8k16.row.col.f32.bf16.bf16.f32 "
        "{%0,%1,%2,%3}, {%4,%5,%6,%7}, {%8,%9}, {%0,%1,%2,%3};"
        : "+f"(acc[0]), "+f"(acc[1]), "+f"(acc[2]), "+f"(acc[3])
        : "r"(a0), "r"(a1), "r"(a2), "r"(a3), "r"(b0), "r"(b1));
}
__device__ __forceinline__ void ldm4(uint32_t* r, const void* p){
    uint32_t a = (uint32_t)__cvta_generic_to_shared(p);
    asm volatile("ldmatrix.sync.aligned.m8n8.x4.shared.b16 {%0,%1,%2,%3}, [%4];"
                 : "=r"(r[0]), "=r"(r[1]), "=r"(r[2]), "=r"(r[3]) : "r"(a));
}
__device__ __forceinline__ void cpa16(void* dst, const void* src){
    uint32_t d = (uint32_t)__cvta_generic_to_shared(dst);
    asm volatile("cp.async.cg.shared.global [%0], [%1], 16;" :: "r"(d), "l"(src));
}
__device__ __forceinline__ uint32_t packbf2(float a, float b){
    __nv_bfloat162 p = __floats2bfloat162_rn(a, b);
    return *(uint32_t*)&p;
}

static __device__ __forceinline__ size_t winrow_to_img(int m){
    int win = m / NN, n = m % NN;
    int b = win >> 6, wi = win & 63;
    int hr = (wi >> 3)*WS + n/WS;
    int wr = (wi & 7)*WS + n%WS;
    int h = hr + SHIFT; if (h >= HH) h -= HH;
    int w = wr + SHIFT; if (w >= WW_) w -= WW_;
    return (size_t)b*LL + (size_t)h*WW_ + w;
}

// ---------------- fused fp32 -> bf16 weight convert ----------------
#define S0 (3*CC*CC)
#define S1 (S0 + CC*CC)
#define S2 (S1 + HID*CC)
#define S3 (S2 + CC*HID)
__global__ void f2bf4_kernel(const float* __restrict__ a, const float* __restrict__ b,
                             const float* __restrict__ c, const float* __restrict__ d,
                             bf16* __restrict__ oa, bf16* __restrict__ ob,
                             bf16* __restrict__ oc, bf16* __restrict__ od){
    int i = blockIdx.x*256 + threadIdx.x;
    if (i < S0)      oa[i]      = __float2bfloat16(a[i]);
    else if (i < S1) ob[i - S0] = __float2bfloat16(b[i - S0]);
    else if (i < S2) oc[i - S1] = __float2bfloat16(c[i - S1]);
    else if (i < S3) od[i - S2] = __float2bfloat16(d[i - S2]);
}

// ---------------- bias table precompute ----------------
__global__ __launch_bounds__(256) void bias_pre_kernel(const float* __restrict__ rpb,
                                                       float* __restrict__ bt)
{
    int wtype = blockIdx.x / NHH;
    int head  = blockIdx.x % NHH;
    int whE = wtype >> 1, wwE = wtype & 1;
    float* o = bt + (size_t)blockIdx.x * 4096;
    for (int idx = threadIdx.x; idx < 4096; idx += 256) {
        int r = idx >> 6, c = idx & 63;
        float v;
        if (c >= NN) v = -1e9f;
        else if (r >= NN) v = 0.f;
        else {
            int ih = r / WS, iw = r % WS;
            int jh = c / WS, jw = c % WS;
            int grh = whE ? ((ih < 4) ? 1 : 2) : 0;
            int grw = wwE ? ((iw < 4) ? 1 : 2) : 0;
            int gch = whE ? ((jh < 4) ? 1 : 2) : 0;
            int gcw = wwE ? ((jw < 4) ? 1 : 2) : 0;
            v = rpb[((ih-jh+6)*13 + (iw-jw+6))*NHH + head]
              + (((grh*3+grw) != (gch*3+gcw)) ? -100.f : 0.f);
        }
        o[idx] = v;
    }
}

// ---------------- LayerNorm: warp per row, single pass ----------------
template<bool GATHER>
__global__ __launch_bounds__(256) void ln_kernel(const float* __restrict__ x,
                                                 const float* __restrict__ gamma,
                                                 const float* __restrict__ beta,
                                                 bf16* __restrict__ out)
{
    int w = threadIdx.x >> 5, lane = threadIdx.x & 31;
    int t = blockIdx.x*8 + w;
    size_t src = GATHER ? winrow_to_img(t) * CC : (size_t)t * CC;
    float v[6];
    #pragma unroll
    for (int i = 0; i < 6; i++) v[i] = x[src + lane + i*32];
    float s = 0.f, q = 0.f;
    #pragma unroll
    for (int i = 0; i < 6; i++) { s += v[i]; q = fmaf(v[i], v[i], q); }
    s = warpSum(s); q = warpSum(q);
    float mean = s * (1.f/CC);
    float rstd = rsqrtf(q * (1.f/CC) - mean*mean + 1e-5f);
    size_t dst = (size_t)t * CC;
    #pragma unroll
    for (int i = 0; i < 6; i++) {
        int ch = lane + i*32;
        out[dst + ch] = __float2bfloat16((v[i] - mean) * rstd * __ldg(gamma+ch) + __ldg(beta+ch));
    }
}

// ================= HMMA GEMM: 128 threads, tile 128x96, warp tile 64x48 =================
// warp grid 2(M) x 2(N). 3-stage cp.async, BK=32. NITER must be divisible by 3.
// EPI 0: +bias -> bf16 | 1: +bias,gelu -> bf16 | 2: +bias +x[imgrow] -> fp32 | 3: +bias +xin -> fp32
#define LDA 40
#define GEMM_SMEM ((3*128*LDA + 3*96*LDA)*2)   // 53760 bytes

template<int EPI, int N, int K>
__global__ __launch_bounds__(128, 3) void mma_gemm(const bf16* __restrict__ A,
                                                   const bf16* __restrict__ Wt,
                                                   const float* __restrict__ bias,
                                                   const float* __restrict__ xin,
                                                   void* __restrict__ outp)
{
    constexpr int NITER = K / 32;
    static_assert(NITER % 3 == 0, "NITER must be divisible by 3");
    extern __shared__ __align__(16) bf16 smem[];
    bf16* AsB = smem;
    bf16* BsB = smem + 3*128*LDA;

    int tid = threadIdx.x;
    int wid = tid >> 5, lane = tid & 31;
    int g = lane >> 2, t4 = lane & 3;
    int wm = (wid >> 1) * 64;        // 2 warps in M, 64 rows each
    int wn = (wid & 1) * 48;         // 2 warps in N, 48 cols each
    int mBase = blockIdx.y * 128;
    int nBase = blockIdx.x * 96;

    const bf16* Abase = A  + (size_t)mBase * K;
    const bf16* Bbase = Wt + (size_t)nBase * K;

    int lr  = tid >> 2;        // 0..31
    int lc8 = tid & 3;         // 16B chunk within 32-wide k

    auto loadTiles = [&](int kt, int s){
        bf16* as = AsB + s*128*LDA;
        bf16* bs = BsB + s*96*LDA;
        #pragma unroll
        for (int i = 0; i < 4; i++) {
            int r = lr + i*32;
            cpa16(&as[r*LDA + lc8*8], Abase + (size_t)r*K + kt + lc8*8);
        }
        #pragma unroll
        for (int i = 0; i < 3; i++) {
            int r = lr + i*32;
            cpa16(&bs[r*LDA + lc8*8], Bbase + (size_t)r*K + kt + lc8*8);
        }
        asm volatile("cp.async.commit_group;" ::: "memory");
    };

    float acc[4][6][4];
    #pragma unroll
    for (int mi=0;mi<4;mi++)
        #pragma unroll
        for (int ni=0;ni<6;ni++)
            #pragma unroll
            for (int c=0;c<4;c++) acc[mi][ni][c] = 0.f;

    int aRowOff = ((lane>>3)&1)*8 + (lane&7);
    int aColOff = ((lane>>4)&1)*8;
    int bRowOff = ((lane>>4)&1)*8 + (lane&7);
    int bColOff = ((lane>>3)&1)*8;

    loadTiles(0, 0);
    loadTiles(32, 1);

    for (int it0 = 0; it0 < NITER; it0 += 3) {
        #pragma unroll
        for (int j = 0; j < 3; j++) {
            int it = it0 + j;
            if (it + 1 < NITER) asm volatile("cp.async.wait_group 1;" ::: "memory");
            else                asm volatile("cp.async.wait_group 0;" ::: "memory");
            __syncthreads();
            if (it + 2 < NITER) loadTiles((it+2)*32, (j+2)%3);

            const bf16* as = AsB + j*128*LDA;
            const bf16* bs = BsB + j*96*LDA;
            #pragma unroll
            for (int ks = 0; ks < 2; ks++) {
                uint32_t af[4][4], bfr[3][4];
                #pragma unroll
                for (int mi = 0; mi < 4; mi++)
                    ldm4(af[mi], &as[(wm + mi*16 + aRowOff)*LDA + ks*16 + aColOff]);
                #pragma unroll
                for (int p = 0; p < 3; p++)
                    ldm4(bfr[p], &bs[(wn + p*16 + bRowOff)*LDA + ks*16 + bColOff]);
                #pragma unroll
                for (int mi = 0; mi < 4; mi++)
                    #pragma unroll
                    for (int p = 0; p < 3; p++) {
                        mma_bf16(acc[mi][2*p  ], af[mi][0], af[mi][1], af[mi][2], af[mi][3],
                                 bfr[p][0], bfr[p][1]);
                        mma_bf16(acc[mi][2*p+1], af[mi][0], af[mi][1], af[mi][2], af[mi][3],
                                 bfr[p][2], bfr[p][3]);
                    }
            }
            __syncthreads();
        }
    }

    // ---------------- epilogue ----------------
    #pragma unroll
    for (int ni = 0; ni < 6; ni++) {
        int n = nBase + wn + ni*8 + t4*2;
        float b0v = __ldg(bias + n), b1v = __ldg(bias + n + 1);
        #pragma unroll
        for (int mi = 0; mi < 4; mi++) {
            #pragma unroll
            for (int h = 0; h < 2; h++) {
                int m = mBase + wm + mi*16 + h*8 + g;
                float u0 = acc[mi][ni][h*2+0] + b0v;
                float u1 = acc[mi][ni][h*2+1] + b1v;
                if (EPI == 1) {
                    float y0 = 0.7978845608028654f * (u0 + 0.044715f*u0*u0*u0);
                    float y1 = 0.7978845608028654f * (u1 + 0.044715f*u1*u1*u1);
                    float t0 = 1.f - 2.f/(__expf(2.f*y0)+1.f);
                    float t1 = 1.f - 2.f/(__expf(2.f*y1)+1.f);
                    u0 = 0.5f*u0*(1.f+t0);
                    u1 = 0.5f*u1*(1.f+t1);
                }
                if (EPI == 0 || EPI == 1) {
                    *(uint32_t*)((bf16*)outp + (size_t)m * N + n) = packbf2(u0, u1);
                } else {
                    size_t drow = (EPI == 2) ? winrow_to_img(m) : (size_t)m;
                    size_t o = drow * CC + n;
                    float2 xv = *(const float2*)(xin + o);
                    float2 ov; ov.x = u0 + xv.x; ov.y = u1 + xv.y;
                    *(float2*)((float*)outp + o) = ov;
                }
            }
        }
    }
}

// ---------------- HMMA windowed attention: one block per (window, head) ----------------
#define ALD 40
#define VLD 72

__global__ __launch_bounds__(128) void attn_mma(const bf16* __restrict__ qkv,
                                                const float* __restrict__ btab,
                                                bf16* __restrict__ out)
{
    __shared__ __align__(16) bf16 sq[64*ALD];
    __shared__ __align__(16) bf16 sk[64*ALD];
    __shared__ __align__(16) bf16 sVt[32*VLD];
    __shared__ __align__(16) float sbias[64*64];

    int win  = blockIdx.x / NHH;
    int head = blockIdx.x % NHH;
    int tid  = threadIdx.x;
    int lane = tid & 31, w = tid >> 5;
    int g = lane >> 2, t4 = lane & 3;

    int wi = win & 63;
    int wtype = (((wi>>3) == 7) ? 2 : 0) + (((wi&7) == 7) ? 1 : 0);
    const float* bt = btab + ((size_t)(wtype*NHH + head))*4096;
    #pragma unroll
    for (int i = 0; i < 8; i++)
        cpa16(&sbias[(tid + i*128)*4], bt + (tid + i*128)*4);
    asm volatile("cp.async.commit_group;" ::: "memory");

    uint32_t* zq = (uint32_t*)sq;
    uint32_t* zk = (uint32_t*)sk;
    uint32_t* zv = (uint32_t*)sVt;
    #pragma unroll
    for (int i = 0; i < 10; i++) { zq[tid + i*128] = 0u; zk[tid + i*128] = 0u; }
    #pragma unroll
    for (int i = 0; i < 9; i++)  { zv[tid + i*128] = 0u; }
    __syncthreads();

    const bf16* base = qkv + (size_t)win*NN*(3*CC) + head*HD;
    const float scale = 0.17677669529663687f;
    for (int i = tid; i < NN*HD; i += 128) {
        int n = i >> 5, d = i & 31;
        float qv = __bfloat162float(base[(size_t)n*(3*CC) + d]) * scale;
        sq[n*ALD + d]  = __float2bfloat16(qv);
        sk[n*ALD + d]  = base[(size_t)n*(3*CC) + CC + d];
        sVt[d*VLD + n] = base[(size_t)n*(3*CC) + 2*CC + d];
    }
    asm volatile("cp.async.wait_group 0;" ::: "memory");
    __syncthreads();

    float sa[8][4];
    #pragma unroll
    for (int nt = 0; nt < 8; nt++)
        #pragma unroll
        for (int c = 0; c < 4; c++) sa[nt][c] = 0.f;

    int r0 = w*16 + g;
    #pragma unroll
    for (int kt = 0; kt < 2; kt++) {
        uint32_t a0 = *(const uint32_t*)&sq[(r0  )*ALD + kt*16 + t4*2    ];
        uint32_t a1 = *(const uint32_t*)&sq[(r0+8)*ALD + kt*16 + t4*2    ];
        uint32_t a2 = *(const uint32_t*)&sq[(r0  )*ALD + kt*16 + t4*2 + 8];
        uint32_t a3 = *(const uint32_t*)&sq[(r0+8)*ALD + kt*16 + t4*2 + 8];
        #pragma unroll
        for (int nt = 0; nt < 8; nt++) {
            int n0 = nt*8 + g;
            uint32_t b0 = *(const uint32_t*)&sk[n0*ALD + kt*16 + t4*2    ];
            uint32_t b1 = *(const uint32_t*)&sk[n0*ALD + kt*16 + t4*2 + 8];
            mma_bf16(sa[nt], a0, a1, a2, a3, b0, b1);
        }
    }

    int rlo = r0, rhi = r0 + 8;
    float mlo = -1e30f, mhi = -1e30f;
    #pragma unroll
    for (int nt = 0; nt < 8; nt++) {
        float2 blo = *(const float2*)&sbias[rlo*64 + nt*8 + t4*2];
        float2 bhi = *(const float2*)&sbias[rhi*64 + nt*8 + t4*2];
        sa[nt][0] += blo.x; sa[nt][1] += blo.y;
        sa[nt][2] += bhi.x; sa[nt][3] += bhi.y;
        mlo = fmaxf(mlo, fmaxf(sa[nt][0], sa[nt][1]));
        mhi = fmaxf(mhi, fmaxf(sa[nt][2], sa[nt][3]));
    }
    mlo = fmaxf(mlo, __shfl_xor_sync(0xffffffffu, mlo, 1));
    mlo = fmaxf(mlo, __shfl_xor_sync(0xffffffffu, mlo, 2));
    mhi = fmaxf(mhi, __shfl_xor_sync(0xffffffffu, mhi, 1));
    mhi = fmaxf(mhi, __shfl_xor_sync(0xffffffffu, mhi, 2));
    float slo = 0.f, shi = 0.f;
    #pragma unroll
    for (int nt = 0; nt < 8; nt++) {
        sa[nt][0] = __expf(sa[nt][0] - mlo);
        sa[nt][1] = __expf(sa[nt][1] - mlo);
        sa[nt][2] = __expf(sa[nt][2] - mhi);
        sa[nt][3] = __expf(sa[nt][3] - mhi);
        slo += sa[nt][0] + sa[nt][1];
        shi += sa[nt][2] + sa[nt][3];
    }
    slo += __shfl_xor_sync(0xffffffffu, slo, 1);
    slo += __shfl_xor_sync(0xffffffffu, slo, 2);
    shi += __shfl_xor_sync(0xffffffffu, shi, 1);
    shi += __shfl_xor_sync(0xffffffffu, shi, 2);
    float ilo = 1.f / slo, ihi = 1.f / shi;

    uint32_t plo[8], phi[8];
    #pragma unroll
    for (int nt = 0; nt < 8; nt++) {
        plo[nt] = packbf2(sa[nt][0]*ilo, sa[nt][1]*ilo);
        phi[nt] = packbf2(sa[nt][2]*ihi, sa[nt][3]*ihi);
    }

    float oacc[4][4];
    #pragma unroll
    for (int nt = 0; nt < 4; nt++)
        #pragma unroll
        for (int c = 0; c < 4; c++) oacc[nt][c] = 0.f;

    #pragma unroll
    for (int kt = 0; kt < 4; kt++) {
        uint32_t a0 = plo[2*kt], a1 = phi[2*kt], a2 = plo[2*kt+1], a3 = phi[2*kt+1];
        #pragma unroll
        for (int nt = 0; nt < 4; nt++) {
            int n0 = nt*8 + g;
            uint32_t b0 = *(const uint32_t*)&sVt[n0*VLD + kt*16 + t4*2    ];
            uint32_t b1 = *(const uint32_t*)&sVt[n0*VLD + kt*16 + t4*2 + 8];
            mma_bf16(oacc[nt], a0, a1, a2, a3, b0, b1);
        }
    }

    #pragma unroll
    for (int nt = 0; nt < 4; nt++) {
        int col = nt*8 + t4*2;
        if (rlo < NN)
            *(uint32_t*)(out + ((size_t)(win*NN + rlo))*CC + head*HD + col) =
                packbf2(oacc[nt][0], oacc[nt][1]);
        if (rhi < NN)
            *(uint32_t*)(out + ((size_t)(win*NN + rhi))*CC + head*HD + col) =
                packbf2(oacc[nt][2], oacc[nt][3]);
    }
}

// ---------------- launch ----------------
extern "C" void kernel_launch(void* const* d_in, const int* in_sizes, int n_in,
                              void* d_out, int out_size)
{
    const float* x      = (const float*)d_in[0];
    const float* qkv_w  = (const float*)d_in[1];
    const float* qkv_b  = (const float*)d_in[2];
    const float* proj_w = (const float*)d_in[3];
    const float* proj_b = (const float*)d_in[4];
    const float* rpb    = (const float*)d_in[5];
    const float* n1g    = (const float*)d_in[6];
    const float* n1b    = (const float*)d_in[7];
    const float* n2g    = (const float*)d_in[8];
    const float* n2b    = (const float*)d_in[9];
    const float* w1     = (const float*)d_in[10];
    const float* b1     = (const float*)d_in[11];
    const float* w2     = (const float*)d_in[12];
    const float* b2     = (const float*)d_in[13];
    float* out = (float*)d_out;

    bf16 *p_ln1, *p_qkvb, *p_attnb, *p_ln2, *p_h1b, *p_wq, *p_wp, *p_w1, *p_w2;
    float *p_x1, *p_bias;
    cudaGetSymbolAddress((void**)&p_ln1,  g_ln1);
    cudaGetSymbolAddress((void**)&p_qkvb, g_qkvb);
    cudaGetSymbolAddress((void**)&p_attnb,g_attnb);
    cudaGetSymbolAddress((void**)&p_ln2,  g_ln2);
    cudaGetSymbolAddress((void**)&p_h1b,  g_h1b);
    cudaGetSymbolAddress((void**)&p_x1,   g_x1);
    cudaGetSymbolAddress((void**)&p_wq,   g_wq);
    cudaGetSymbolAddress((void**)&p_wp,   g_wp);
    cudaGetSymbolAddress((void**)&p_w1,   g_w1);
    cudaGetSymbolAddress((void**)&p_w2,   g_w2);
    cudaGetSymbolAddress((void**)&p_bias, g_bias);

    cudaFuncSetAttribute(mma_gemm<0, 3*CC, CC>, cudaFuncAttributeMaxDynamicSharedMemorySize, GEMM_SMEM);
    cudaFuncSetAttribute(mma_gemm<2, CC, CC>,   cudaFuncAttributeMaxDynamicSharedMemorySize, GEMM_SMEM);
    cudaFuncSetAttribute(mma_gemm<1, HID, CC>,  cudaFuncAttributeMaxDynamicSharedMemorySize, GEMM_SMEM);
    cudaFuncSetAttribute(mma_gemm<3, CC, HID>,  cudaFuncAttributeMaxDynamicSharedMemorySize, GEMM_SMEM);

    // 0) weights -> bf16 + bias tables
    f2bf4_kernel<<<(S3 + 255)/256, 256>>>(qkv_w, proj_w, w1, w2, p_wq, p_wp, p_w1, p_w2);
    bias_pre_kernel<<<4*NHH, 256>>>(rpb, p_bias);

    // 1) LN1 + roll + window partition -> bf16
    ln_kernel<true><<<TOK/8, 256>>>(x, n1g, n1b, p_ln1);

    // 2) qkv GEMM
    mma_gemm<0, 3*CC, CC><<<dim3(6, TOK/128), 128, GEMM_SMEM>>>(p_ln1, p_wq, qkv_b, nullptr, p_qkvb);

    // 3) windowed attention (HMMA)
    attn_mma<<<BW*NHH, 128>>>(p_qkvb, p_bias, p_attnb);

    // 4) proj GEMM + window reverse + residual -> g_x1 (fp32)
    mma_gemm<2, CC, CC><<<dim3(2, TOK/128), 128, GEMM_SMEM>>>(p_attnb, p_wp, proj_b, x, p_x1);

    // 5) LN2 -> bf16
    ln_kernel<false><<<TOK/8, 256>>>(p_x1, n2g, n2b, p_ln2);

    // 6) fc1 + gelu -> bf16
    mma_gemm<1, HID, CC><<<dim3(8, TOK/128), 128, GEMM_SMEM>>>(p_ln2, p_w1, b1, nullptr, p_h1b);

    // 7) fc2 + bias + residual -> d_out (fp32)
    mma_gemm<3, CC, HID><<<dim3(2, TOK/128), 128, GEMM_SMEM>>>(p_h1b, p_w2, b2, p_x1, out);
}

// round 15
// speedup vs baseline: 1.0369x; 1.0060x over previous
#include <cuda_runtime.h>
#include <cuda_bf16.h>
#include <math.h>
#include <stdint.h>

// ---------------- problem constants ----------------
#define BSZ   32
#define HH    56
#define WW_   56
#define CC    192
#define LL    (HH*WW_)          // 3136
#define WS    7
#define NN    49
#define NHH   6
#define HD    32
#define SHIFT 3
#define NWIN  64
#define BW    (BSZ*NWIN)        // 2048
#define TOK   (BW*NN)           // 100352
#define HID   768

typedef __nv_bfloat16 bf16;

// ---------------- scratch (static device, no allocs) ----------------
__device__ __align__(256) bf16 g_ln1 [(size_t)TOK*CC];
__device__ __align__(256) bf16 g_qkvb[(size_t)TOK*3*CC];
__device__ __align__(256) bf16 g_attnb[(size_t)TOK*CC];
__device__ __align__(256) bf16 g_ln2 [(size_t)TOK*CC];
__device__ __align__(256) bf16 g_h1b [(size_t)TOK*HID];
__device__ __align__(256) float g_x1 [(size_t)TOK*CC];
__device__ __align__(256) bf16 g_wq[3*CC*CC];
__device__ __align__(256) bf16 g_wp[CC*CC];
__device__ __align__(256) bf16 g_w1[HID*CC];
__device__ __align__(256) bf16 g_w2[CC*HID];
__device__ __align__(256) float g_bias[4*NHH*64*64];   // precomputed bias+mask tables

// ---------------- helpers ----------------
__device__ __forceinline__ float warpSum(float v){
    #pragma unroll
    for (int o=16;o;o>>=1) v += __shfl_xor_sync(0xffffffffu, v, o);
    return v;
}
// non-volatile: pure register op, lets the compiler interleave with LDSM
__device__ __forceinline__ void mma_bf16(float* acc, uint32_t a0, uint32_t a1, uint32_t a2, uint32_t a3,
                                         uint32_t b0, uint32_t b1){
    asm("mma.sync.aligned.m16n8k16.row.col.f32.bf16.bf16.f32 "
        "{%0,%1,%2,%3}, {%4,%5,%6,%7}, {%8,%9}, {%0,%1,%2,%3};"
        : "+f"(acc[0]), "+f"(acc[1]), "+f"(acc[2]), "+f"(acc[3])
        : "r"(a0), "r"(a1), "r"(a2), "r"(a3), "r"(b0), "r"(b1));
}
__device__ __forceinline__ void ldm4(uint32_t* r, const void* p){
    uint32_t a = (uint32_t)__cvta_generic_to_shared(p);
    asm volatile("ldmatrix.sync.aligned.m8n8.x4.shared.b16 {%0,%1,%2,%3}, [%4];"
                 : "=r"(r[0]), "=r"(r[1]), "=r"(r[2]), "=r"(r[3]) : "r"(a));
}
__device__ __forceinline__ void cpa16(void* dst, const void* src){
    uint32_t d = (uint32_t)__cvta_generic_to_shared(dst);
    asm volatile("cp.async.cg.shared.global [%0], [%1], 16;" :: "r"(d), "l"(src));
}
__device__ __forceinline__ uint32_t packbf2(float a, float b){
    __nv_bfloat162 p = __floats2bfloat162_rn(a, b);
    return *(uint32_t*)&p;
}

static __device__ __forceinline__ size_t winrow_to_img(int m){
    int win = m / NN, n = m % NN;
    int b = win >> 6, wi = win & 63;
    int hr = (wi >> 3)*WS + n/WS;
    int wr = (wi & 7)*WS + n%WS;
    int h = hr + SHIFT; if (h >= HH) h -= HH;
    int w = wr + SHIFT; if (w >= WW_) w -= WW_;
    return (size_t)b*LL + (size_t)h*WW_ + w;
}

// ---------------- fused fp32 -> bf16 weight convert ----------------
#define S0 (3*CC*CC)
#define S1 (S0 + CC*CC)
#define S2 (S1 + HID*CC)
#define S3 (S2 + CC*HID)
__global__ void f2bf4_kernel(const float* __restrict__ a, const float* __restrict__ b,
                             const float* __restrict__ c, const float* __restrict__ d,
                             bf16* __restrict__ oa, bf16* __restrict__ ob,
                             bf16* __restrict__ oc, bf16* __restrict__ od){
    int i = blockIdx.x*256 + threadIdx.x;
    if (i < S0)      oa[i]      = __float2bfloat16(a[i]);
    else if (i < S1) ob[i - S0] = __float2bfloat16(b[i - S0]);
    else if (i < S2) oc[i - S1] = __float2bfloat16(c[i - S1]);
    else if (i < S3) od[i - S2] = __float2bfloat16(d[i - S2]);
}

// ---------------- bias table precompute ----------------
__global__ __launch_bounds__(256) void bias_pre_kernel(const float* __restrict__ rpb,
                                                       float* __restrict__ bt)
{
    int wtype = blockIdx.x / NHH;
    int head  = blockIdx.x % NHH;
    int whE = wtype >> 1, wwE = wtype & 1;
    float* o = bt + (size_t)blockIdx.x * 4096;
    for (int idx = threadIdx.x; idx < 4096; idx += 256) {
        int r = idx >> 6, c = idx & 63;
        float v;
        if (c >= NN) v = -1e9f;
        else if (r >= NN) v = 0.f;
        else {
            int ih = r / WS, iw = r % WS;
            int jh = c / WS, jw = c % WS;
            int grh = whE ? ((ih < 4) ? 1 : 2) : 0;
            int grw = wwE ? ((iw < 4) ? 1 : 2) : 0;
            int gch = whE ? ((jh < 4) ? 1 : 2) : 0;
            int gcw = wwE ? ((jw < 4) ? 1 : 2) : 0;
            v = rpb[((ih-jh+6)*13 + (iw-jw+6))*NHH + head]
              + (((grh*3+grw) != (gch*3+gcw)) ? -100.f : 0.f);
        }
        o[idx] = v;
    }
}

// ---------------- LayerNorm: warp per row, single pass ----------------
template<bool GATHER>
__global__ __launch_bounds__(256) void ln_kernel(const float* __restrict__ x,
                                                 const float* __restrict__ gamma,
                                                 const float* __restrict__ beta,
                                                 bf16* __restrict__ out)
{
    int w = threadIdx.x >> 5, lane = threadIdx.x & 31;
    int t = blockIdx.x*8 + w;
    size_t src = GATHER ? winrow_to_img(t) * CC : (size_t)t * CC;
    float v[6];
    #pragma unroll
    for (int i = 0; i < 6; i++) v[i] = x[src + lane + i*32];
    float s = 0.f, q = 0.f;
    #pragma unroll
    for (int i = 0; i < 6; i++) { s += v[i]; q = fmaf(v[i], v[i], q); }
    s = warpSum(s); q = warpSum(q);
    float mean = s * (1.f/CC);
    float rstd = rsqrtf(q * (1.f/CC) - mean*mean + 1e-5f);
    size_t dst = (size_t)t * CC;
    #pragma unroll
    for (int i = 0; i < 6; i++) {
        int ch = lane + i*32;
        out[dst + ch] = __float2bfloat16((v[i] - mean) * rstd * __ldg(gamma+ch) + __ldg(beta+ch));
    }
}

// ================= HMMA GEMM: 128 threads, tile 128x96, warp tile 64x48 =================
// warp grid 2(M) x 2(N). 3-stage cp.async, BK=32, ONE barrier per K-iter.
// EPI 0: +bias -> bf16 | 1: +bias,gelu -> bf16 | 2: +bias +x[imgrow] -> fp32 | 3: +bias +xin -> fp32
#define LDA 40
#define GEMM_SMEM ((3*128*LDA + 3*96*LDA)*2)   // 53760 bytes

template<int EPI, int N, int K>
__global__ __launch_bounds__(128, 3) void mma_gemm(const bf16* __restrict__ A,
                                                   const bf16* __restrict__ Wt,
                                                   const float* __restrict__ bias,
                                                   const float* __restrict__ xin,
                                                   void* __restrict__ outp)
{
    constexpr int NITER = K / 32;
    static_assert(NITER % 3 == 0, "NITER must be divisible by 3");
    extern __shared__ __align__(16) bf16 smem[];
    bf16* AsB = smem;
    bf16* BsB = smem + 3*128*LDA;

    int tid = threadIdx.x;
    int wid = tid >> 5, lane = tid & 31;
    int g = lane >> 2, t4 = lane & 3;
    int wm = (wid >> 1) * 64;        // 2 warps in M, 64 rows each
    int wn = (wid & 1) * 48;         // 2 warps in N, 48 cols each
    int mBase = blockIdx.y * 128;
    int nBase = blockIdx.x * 96;

    const bf16* Abase = A  + (size_t)mBase * K;
    const bf16* Bbase = Wt + (size_t)nBase * K;

    int lr  = tid >> 2;        // 0..31
    int lc8 = tid & 3;         // 16B chunk within 32-wide k

    auto loadTiles = [&](int kt, int s){
        bf16* as = AsB + s*128*LDA;
        bf16* bs = BsB + s*96*LDA;
        #pragma unroll
        for (int i = 0; i < 4; i++) {
            int r = lr + i*32;
            cpa16(&as[r*LDA + lc8*8], Abase + (size_t)r*K + kt + lc8*8);
        }
        #pragma unroll
        for (int i = 0; i < 3; i++) {
            int r = lr + i*32;
            cpa16(&bs[r*LDA + lc8*8], Bbase + (size_t)r*K + kt + lc8*8);
        }
        asm volatile("cp.async.commit_group;" ::: "memory");
    };

    float acc[4][6][4];
    #pragma unroll
    for (int mi=0;mi<4;mi++)
        #pragma unroll
        for (int ni=0;ni<6;ni++)
            #pragma unroll
            for (int c=0;c<4;c++) acc[mi][ni][c] = 0.f;

    int aRowOff = ((lane>>3)&1)*8 + (lane&7);
    int aColOff = ((lane>>4)&1)*8;
    int bRowOff = ((lane>>4)&1)*8 + (lane&7);
    int bColOff = ((lane>>3)&1)*8;

    loadTiles(0, 0);
    loadTiles(32, 1);

    for (int it0 = 0; it0 < NITER; it0 += 3) {
        #pragma unroll
        for (int j = 0; j < 3; j++) {
            int it = it0 + j;
            if (it + 1 < NITER) asm volatile("cp.async.wait_group 1;" ::: "memory");
            else                asm volatile("cp.async.wait_group 0;" ::: "memory");
            // Single barrier per iter: also guarantees every warp finished the
            // previous iter's compute, so loading into stage (it+2)%3 (last read
            // during iter it-1) is safe.
            __syncthreads();
            if (it + 2 < NITER) loadTiles((it+2)*32, (j+2)%3);

            const bf16* as = AsB + j*128*LDA;
            const bf16* bs = BsB + j*96*LDA;

            // Load ALL fragments for this stage (both ks steps) up front,
            // then issue all MMAs — LDSM latency hides under MMA issue.
            uint32_t af[2][4][4], bfr[2][3][4];
            #pragma unroll
            for (int ks = 0; ks < 2; ks++) {
                #pragma unroll
                for (int mi = 0; mi < 4; mi++)
                    ldm4(af[ks][mi], &as[(wm + mi*16 + aRowOff)*LDA + ks*16 + aColOff]);
                #pragma unroll
                for (int p = 0; p < 3; p++)
                    ldm4(bfr[ks][p], &bs[(wn + p*16 + bRowOff)*LDA + ks*16 + bColOff]);
            }
            #pragma unroll
            for (int ks = 0; ks < 2; ks++)
                #pragma unroll
                for (int mi = 0; mi < 4; mi++)
                    #pragma unroll
                    for (int p = 0; p < 3; p++) {
                        mma_bf16(acc[mi][2*p  ], af[ks][mi][0], af[ks][mi][1], af[ks][mi][2], af[ks][mi][3],
                                 bfr[ks][p][0], bfr[ks][p][1]);
                        mma_bf16(acc[mi][2*p+1], af[ks][mi][0], af[ks][mi][1], af[ks][mi][2], af[ks][mi][3],
                                 bfr[ks][p][2], bfr[ks][p][3]);
                    }
        }
    }

    // ---------------- epilogue ----------------
    #pragma unroll
    for (int ni = 0; ni < 6; ni++) {
        int n = nBase + wn + ni*8 + t4*2;
        float b0v = __ldg(bias + n), b1v = __ldg(bias + n + 1);
        #pragma unroll
        for (int mi = 0; mi < 4; mi++) {
            #pragma unroll
            for (int h = 0; h < 2; h++) {
                int m = mBase + wm + mi*16 + h*8 + g;
                float u0 = acc[mi][ni][h*2+0] + b0v;
                float u1 = acc[mi][ni][h*2+1] + b1v;
                if (EPI == 1) {
                    float y0 = 0.7978845608028654f * (u0 + 0.044715f*u0*u0*u0);
                    float y1 = 0.7978845608028654f * (u1 + 0.044715f*u1*u1*u1);
                    float t0 = 1.f - 2.f/(__expf(2.f*y0)+1.f);
                    float t1 = 1.f - 2.f/(__expf(2.f*y1)+1.f);
                    u0 = 0.5f*u0*(1.f+t0);
                    u1 = 0.5f*u1*(1.f+t1);
                }
                if (EPI == 0 || EPI == 1) {
                    *(uint32_t*)((bf16*)outp + (size_t)m * N + n) = packbf2(u0, u1);
                } else {
                    size_t drow = (EPI == 2) ? winrow_to_img(m) : (size_t)m;
                    size_t o = drow * CC + n;
                    float2 xv = *(const float2*)(xin + o);
                    float2 ov; ov.x = u0 + xv.x; ov.y = u1 + xv.y;
                    *(float2*)((float*)outp + o) = ov;
                }
            }
        }
    }
}

// ---------------- HMMA windowed attention: one block per (window, head) ----------------
#define ALD 40
#define VLD 72

__global__ __launch_bounds__(128) void attn_mma(const bf16* __restrict__ qkv,
                                                const float* __restrict__ btab,
                                                bf16* __restrict__ out)
{
    __shared__ __align__(16) bf16 sq[64*ALD];
    __shared__ __align__(16) bf16 sk[64*ALD];
    __shared__ __align__(16) bf16 sVt[32*VLD];
    __shared__ __align__(16) float sbias[64*64];

    int win  = blockIdx.x / NHH;
    int head = blockIdx.x % NHH;
    int tid  = threadIdx.x;
    int lane = tid & 31, w = tid >> 5;
    int g = lane >> 2, t4 = lane & 3;

    int wi = win & 63;
    int wtype = (((wi>>3) == 7) ? 2 : 0) + (((wi&7) == 7) ? 1 : 0);
    const float* bt = btab + ((size_t)(wtype*NHH + head))*4096;
    #pragma unroll
    for (int i = 0; i < 8; i++)
        cpa16(&sbias[(tid + i*128)*4], bt + (tid + i*128)*4);
    asm volatile("cp.async.commit_group;" ::: "memory");

    uint32_t* zq = (uint32_t*)sq;
    uint32_t* zk = (uint32_t*)sk;
    uint32_t* zv = (uint32_t*)sVt;
    #pragma unroll
    for (int i = 0; i < 10; i++) { zq[tid + i*128] = 0u; zk[tid + i*128] = 0u; }
    #pragma unroll
    for (int i = 0; i < 9; i++)  { zv[tid + i*128] = 0u; }
    __syncthreads();

    const bf16* base = qkv + (size_t)win*NN*(3*CC) + head*HD;
    const float scale = 0.17677669529663687f;
    for (int i = tid; i < NN*HD; i += 128) {
        int n = i >> 5, d = i & 31;
        float qv = __bfloat162float(base[(size_t)n*(3*CC) + d]) * scale;
        sq[n*ALD + d]  = __float2bfloat16(qv);
        sk[n*ALD + d]  = base[(size_t)n*(3*CC) + CC + d];
        sVt[d*VLD + n] = base[(size_t)n*(3*CC) + 2*CC + d];
    }
    asm volatile("cp.async.wait_group 0;" ::: "memory");
    __syncthreads();

    float sa[8][4];
    #pragma unroll
    for (int nt = 0; nt < 8; nt++)
        #pragma unroll
        for (int c = 0; c < 4; c++) sa[nt][c] = 0.f;

    int r0 = w*16 + g;
    #pragma unroll
    for (int kt = 0; kt < 2; kt++) {
        uint32_t a0 = *(const uint32_t*)&sq[(r0  )*ALD + kt*16 + t4*2    ];
        uint32_t a1 = *(const uint32_t*)&sq[(r0+8)*ALD + kt*16 + t4*2    ];
        uint32_t a2 = *(const uint32_t*)&sq[(r0  )*ALD + kt*16 + t4*2 + 8];
        uint32_t a3 = *(const uint32_t*)&sq[(r0+8)*ALD + kt*16 + t4*2 + 8];
        #pragma unroll
        for (int nt = 0; nt < 8; nt++) {
            int n0 = nt*8 + g;
            uint32_t b0 = *(const uint32_t*)&sk[n0*ALD + kt*16 + t4*2    ];
            uint32_t b1 = *(const uint32_t*)&sk[n0*ALD + kt*16 + t4*2 + 8];
            mma_bf16(sa[nt], a0, a1, a2, a3, b0, b1);
        }
    }

    int rlo = r0, rhi = r0 + 8;
    float mlo = -1e30f, mhi = -1e30f;
    #pragma unroll
    for (int nt = 0; nt < 8; nt++) {
        float2 blo = *(const float2*)&sbias[rlo*64 + nt*8 + t4*2];
        float2 bhi = *(const float2*)&sbias[rhi*64 + nt*8 + t4*2];
        sa[nt][0] += blo.x; sa[nt][1] += blo.y;
        sa[nt][2] += bhi.x; sa[nt][3] += bhi.y;
        mlo = fmaxf(mlo, fmaxf(sa[nt][0], sa[nt][1]));
        mhi = fmaxf(mhi, fmaxf(sa[nt][2], sa[nt][3]));
    }
    mlo = fmaxf(mlo, __shfl_xor_sync(0xffffffffu, mlo, 1));
    mlo = fmaxf(mlo, __shfl_xor_sync(0xffffffffu, mlo, 2));
    mhi = fmaxf(mhi, __shfl_xor_sync(0xffffffffu, mhi, 1));
    mhi = fmaxf(mhi, __shfl_xor_sync(0xffffffffu, mhi, 2));
    float slo = 0.f, shi = 0.f;
    #pragma unroll
    for (int nt = 0; nt < 8; nt++) {
        sa[nt][0] = __expf(sa[nt][0] - mlo);
        sa[nt][1] = __expf(sa[nt][1] - mlo);
        sa[nt][2] = __expf(sa[nt][2] - mhi);
        sa[nt][3] = __expf(sa[nt][3] - mhi);
        slo += sa[nt][0] + sa[nt][1];
        shi += sa[nt][2] + sa[nt][3];
    }
    slo += __shfl_xor_sync(0xffffffffu, slo, 1);
    slo += __shfl_xor_sync(0xffffffffu, slo, 2);
    shi += __shfl_xor_sync(0xffffffffu, shi, 1);
    shi += __shfl_xor_sync(0xffffffffu, shi, 2);
    float ilo = 1.f / slo, ihi = 1.f / shi;

    uint32_t plo[8], phi[8];
    #pragma unroll
    for (int nt = 0; nt < 8; nt++) {
        plo[nt] = packbf2(sa[nt][0]*ilo, sa[nt][1]*ilo);
        phi[nt] = packbf2(sa[nt][2]*ihi, sa[nt][3]*ihi);
    }

    float oacc[4][4];
    #pragma unroll
    for (int nt = 0; nt < 4; nt++)
        #pragma unroll
        for (int c = 0; c < 4; c++) oacc[nt][c] = 0.f;

    #pragma unroll
    for (int kt = 0; kt < 4; kt++) {
        uint32_t a0 = plo[2*kt], a1 = phi[2*kt], a2 = plo[2*kt+1], a3 = phi[2*kt+1];
        #pragma unroll
        for (int nt = 0; nt < 4; nt++) {
            int n0 = nt*8 + g;
            uint32_t b0 = *(const uint32_t*)&sVt[n0*VLD + kt*16 + t4*2    ];
            uint32_t b1 = *(const uint32_t*)&sVt[n0*VLD + kt*16 + t4*2 + 8];
            mma_bf16(oacc[nt], a0, a1, a2, a3, b0, b1);
        }
    }

    #pragma unroll
    for (int nt = 0; nt < 4; nt++) {
        int col = nt*8 + t4*2;
        if (rlo < NN)
            *(uint32_t*)(out + ((size_t)(win*NN + rlo))*CC + head*HD + col) =
                packbf2(oacc[nt][0], oacc[nt][1]);
        if (rhi < NN)
            *(uint32_t*)(out + ((size_t)(win*NN + rhi))*CC + head*HD + col) =
                packbf2(oacc[nt][2], oacc[nt][3]);
    }
}

// ---------------- launch ----------------
extern "C" void kernel_launch(void* const* d_in, const int* in_sizes, int n_in,
                              void* d_out, int out_size)
{
    const float* x      = (const float*)d_in[0];
    const float* qkv_w  = (const float*)d_in[1];
    const float* qkv_b  = (const float*)d_in[2];
    const float* proj_w = (const float*)d_in[3];
    const float* proj_b = (const float*)d_in[4];
    const float* rpb    = (const float*)d_in[5];
    const float* n1g    = (const float*)d_in[6];
    const float* n1b    = (const float*)d_in[7];
    const float* n2g    = (const float*)d_in[8];
    const float* n2b    = (const float*)d_in[9];
    const float* w1     = (const float*)d_in[10];
    const float* b1     = (const float*)d_in[11];
    const float* w2     = (const float*)d_in[12];
    const float* b2     = (const float*)d_in[13];
    float* out = (float*)d_out;

    bf16 *p_ln1, *p_qkvb, *p_attnb, *p_ln2, *p_h1b, *p_wq, *p_wp, *p_w1, *p_w2;
    float *p_x1, *p_bias;
    cudaGetSymbolAddress((void**)&p_ln1,  g_ln1);
    cudaGetSymbolAddress((void**)&p_qkvb, g_qkvb);
    cudaGetSymbolAddress((void**)&p_attnb,g_attnb);
    cudaGetSymbolAddress((void**)&p_ln2,  g_ln2);
    cudaGetSymbolAddress((void**)&p_h1b,  g_h1b);
    cudaGetSymbolAddress((void**)&p_x1,   g_x1);
    cudaGetSymbolAddress((void**)&p_wq,   g_wq);
    cudaGetSymbolAddress((void**)&p_wp,   g_wp);
    cudaGetSymbolAddress((void**)&p_w1,   g_w1);
    cudaGetSymbolAddress((void**)&p_w2,   g_w2);
    cudaGetSymbolAddress((void**)&p_bias, g_bias);

    cudaFuncSetAttribute(mma_gemm<0, 3*CC, CC>, cudaFuncAttributeMaxDynamicSharedMemorySize, GEMM_SMEM);
    cudaFuncSetAttribute(mma_gemm<2, CC, CC>,   cudaFuncAttributeMaxDynamicSharedMemorySize, GEMM_SMEM);
    cudaFuncSetAttribute(mma_gemm<1, HID, CC>,  cudaFuncAttributeMaxDynamicSharedMemorySize, GEMM_SMEM);
    cudaFuncSetAttribute(mma_gemm<3, CC, HID>,  cudaFuncAttributeMaxDynamicSharedMemorySize, GEMM_SMEM);

    // 0) weights -> bf16 + bias tables
    f2bf4_kernel<<<(S3 + 255)/256, 256>>>(qkv_w, proj_w, w1, w2, p_wq, p_wp, p_w1, p_w2);
    bias_pre_kernel<<<4*NHH, 256>>>(rpb, p_bias);

    // 1) LN1 + roll + window partition -> bf16
    ln_kernel<true><<<TOK/8, 256>>>(x, n1g, n1b, p_ln1);

    // 2) qkv GEMM
    mma_gemm<0, 3*CC, CC><<<dim3(6, TOK/128), 128, GEMM_SMEM>>>(p_ln1, p_wq, qkv_b, nullptr, p_qkvb);

    // 3) windowed attention (HMMA)
    attn_mma<<<BW*NHH, 128>>>(p_qkvb, p_bias, p_attnb);

    // 4) proj GEMM + window reverse + residual -> g_x1 (fp32)
    mma_gemm<2, CC, CC><<<dim3(2, TOK/128), 128, GEMM_SMEM>>>(p_attnb, p_wp, proj_b, x, p_x1);

    // 5) LN2 -> bf16
    ln_kernel<false><<<TOK/8, 256>>>(p_x1, n2g, n2b, p_ln2);

    // 6) fc1 + gelu -> bf16
    mma_gemm<1, HID, CC><<<dim3(8, TOK/128), 128, GEMM_SMEM>>>(p_ln2, p_w1, b1, nullptr, p_h1b);

    // 7) fc2 + bias + residual -> d_out (fp32)
    mma_gemm<3, CC, HID><<<dim3(2, TOK/128), 128, GEMM_SMEM>>>(p_h1b, p_w2, b2, p_x1, out);
}

// round 17
// speedup vs baseline: 1.0445x; 1.0073x over previous
#include <cuda_runtime.h>
#include <cuda_bf16.h>
#include <math.h>
#include <stdint.h>

// ---------------- problem constants ----------------
#define BSZ   32
#define HH    56
#define WW_   56
#define CC    192
#define LL    (HH*WW_)          // 3136
#define WS    7
#define NN    49
#define NHH   6
#define HD    32
#define SHIFT 3
#define NWIN  64
#define BW    (BSZ*NWIN)        // 2048
#define TOK   (BW*NN)           // 100352
#define HID   768

typedef __nv_bfloat16 bf16;

// ---------------- scratch (static device, no allocs) ----------------
__device__ __align__(256) bf16 g_ln1 [(size_t)TOK*CC];
__device__ __align__(256) bf16 g_qkvb[(size_t)TOK*3*CC];
__device__ __align__(256) bf16 g_attnb[(size_t)TOK*CC];
__device__ __align__(256) bf16 g_ln2 [(size_t)TOK*CC];
__device__ __align__(256) bf16 g_h1b [(size_t)TOK*HID];
__device__ __align__(256) float g_x1 [(size_t)TOK*CC];
__device__ __align__(256) bf16 g_wq[3*CC*CC];
__device__ __align__(256) bf16 g_wp[CC*CC];
__device__ __align__(256) bf16 g_w1[HID*CC];
__device__ __align__(256) bf16 g_w2[CC*HID];
__device__ __align__(256) float g_bias[4*NHH*64*64];   // precomputed bias+mask tables

// ---------------- helpers ----------------
__device__ __forceinline__ float warpSum(float v){
    #pragma unroll
    for (int o=16;o;o>>=1) v += __shfl_xor_sync(0xffffffffu, v, o);
    return v;
}
__device__ __forceinline__ void mma_bf16(float* acc, uint32_t a0, uint32_t a1, uint32_t a2, uint32_t a3,
                                         uint32_t b0, uint32_t b1){
    asm("mma.sync.aligned.m16n8k16.row.col.f32.bf16.bf16.f32 "
        "{%0,%1,%2,%3}, {%4,%5,%6,%7}, {%8,%9}, {%0,%1,%2,%3};"
        : "+f"(acc[0]), "+f"(acc[1]), "+f"(acc[2]), "+f"(acc[3])
        : "r"(a0), "r"(a1), "r"(a2), "r"(a3), "r"(b0), "r"(b1));
}
__device__ __forceinline__ void ldm4(uint32_t* r, const void* p){
    uint32_t a = (uint32_t)__cvta_generic_to_shared(p);
    asm volatile("ldmatrix.sync.aligned.m8n8.x4.shared.b16 {%0,%1,%2,%3}, [%4];"
                 : "=r"(r[0]), "=r"(r[1]), "=r"(r[2]), "=r"(r[3]) : "r"(a));
}
__device__ __forceinline__ void cpa16(void* dst, const void* src){
    uint32_t d = (uint32_t)__cvta_generic_to_shared(dst);
    asm volatile("cp.async.cg.shared.global [%0], [%1], 16;" :: "r"(d), "l"(src));
}
__device__ __forceinline__ uint32_t packbf2(float a, float b){
    __nv_bfloat162 p = __floats2bfloat162_rn(a, b);
    return *(uint32_t*)&p;
}

static __device__ __forceinline__ size_t winrow_to_img(int m){
    int win = m / NN, n = m % NN;
    int b = win >> 6, wi = win & 63;
    int hr = (wi >> 3)*WS + n/WS;
    int wr = (wi & 7)*WS + n%WS;
    int h = hr + SHIFT; if (h >= HH) h -= HH;
    int w = wr + SHIFT; if (w >= WW_) w -= WW_;
    return (size_t)b*LL + (size_t)h*WW_ + w;
}

// ---------------- fused fp32 -> bf16 weight convert ----------------
#define S0 (3*CC*CC)
#define S1 (S0 + CC*CC)
#define S2 (S1 + HID*CC)
#define S3 (S2 + CC*HID)
__global__ void f2bf4_kernel(const float* __restrict__ a, const float* __restrict__ b,
                             const float* __restrict__ c, const float* __restrict__ d,
                             bf16* __restrict__ oa, bf16* __restrict__ ob,
                             bf16* __restrict__ oc, bf16* __restrict__ od){
    int i = blockIdx.x*256 + threadIdx.x;
    if (i < S0)      oa[i]      = __float2bfloat16(a[i]);
    else if (i < S1) ob[i - S0] = __float2bfloat16(b[i - S0]);
    else if (i < S2) oc[i - S1] = __float2bfloat16(c[i - S1]);
    else if (i < S3) od[i - S2] = __float2bfloat16(d[i - S2]);
}

// ---------------- bias table precompute ----------------
__global__ __launch_bounds__(256) void bias_pre_kernel(const float* __restrict__ rpb,
                                                       float* __restrict__ bt)
{
    int wtype = blockIdx.x / NHH;
    int head  = blockIdx.x % NHH;
    int whE = wtype >> 1, wwE = wtype & 1;
    float* o = bt + (size_t)blockIdx.x * 4096;
    for (int idx = threadIdx.x; idx < 4096; idx += 256) {
        int r = idx >> 6, c = idx & 63;
        float v;
        if (c >= NN) v = -1e9f;
        else if (r >= NN) v = 0.f;
        else {
            int ih = r / WS, iw = r % WS;
            int jh = c / WS, jw = c % WS;
            int grh = whE ? ((ih < 4) ? 1 : 2) : 0;
            int grw = wwE ? ((iw < 4) ? 1 : 2) : 0;
            int gch = whE ? ((jh < 4) ? 1 : 2) : 0;
            int gcw = wwE ? ((jw < 4) ? 1 : 2) : 0;
            v = rpb[((ih-jh+6)*13 + (iw-jw+6))*NHH + head]
              + (((grh*3+grw) != (gch*3+gcw)) ? -100.f : 0.f);
        }
        o[idx] = v;
    }
}

// ---------------- LayerNorm: warp per row, single pass ----------------
template<bool GATHER>
__global__ __launch_bounds__(256) void ln_kernel(const float* __restrict__ x,
                                                 const float* __restrict__ gamma,
                                                 const float* __restrict__ beta,
                                                 bf16* __restrict__ out)
{
    int w = threadIdx.x >> 5, lane = threadIdx.x & 31;
    int t = blockIdx.x*8 + w;
    size_t src = GATHER ? winrow_to_img(t) * CC : (size_t)t * CC;
    float v[6];
    #pragma unroll
    for (int i = 0; i < 6; i++) v[i] = x[src + lane + i*32];
    float s = 0.f, q = 0.f;
    #pragma unroll
    for (int i = 0; i < 6; i++) { s += v[i]; q = fmaf(v[i], v[i], q); }
    s = warpSum(s); q = warpSum(q);
    float mean = s * (1.f/CC);
    float rstd = rsqrtf(q * (1.f/CC) - mean*mean + 1e-5f);
    size_t dst = (size_t)t * CC;
    #pragma unroll
    for (int i = 0; i < 6; i++) {
        int ch = lane + i*32;
        out[dst + ch] = __float2bfloat16((v[i] - mean) * rstd * __ldg(gamma+ch) + __ldg(beta+ch));
    }
}

// ================= HMMA GEMM: 128 threads, tile 128x96, warp tile 64x48 =================
// warp grid 2(M) x 2(N). FOUR-stage cp.async ring, wait_group 2 steady state
// (3 loads in flight -> ~2.5 iters of latency coverage), one barrier per K-iter.
// EPI 0: +bias -> bf16 | 1: +bias,gelu -> bf16 | 2: +bias +x[imgrow] -> fp32 | 3: +bias +xin -> fp32
#define LDA 40
#define NSTG 4
#define GEMM_SMEM ((NSTG*128*LDA + NSTG*96*LDA)*2)   // 71680 bytes

template<int EPI, int N, int K>
__global__ __launch_bounds__(128, 3) void mma_gemm(const bf16* __restrict__ A,
                                                   const bf16* __restrict__ Wt,
                                                   const float* __restrict__ bias,
                                                   const float* __restrict__ xin,
                                                   void* __restrict__ outp)
{
    constexpr int NITER = K / 32;
    static_assert(NITER >= 4, "need at least 4 K-iters");
    extern __shared__ __align__(16) bf16 smem[];
    bf16* AsB = smem;
    bf16* BsB = smem + NSTG*128*LDA;

    int tid = threadIdx.x;
    int wid = tid >> 5, lane = tid & 31;
    int g = lane >> 2, t4 = lane & 3;
    int wm = (wid >> 1) * 64;        // 2 warps in M, 64 rows each
    int wn = (wid & 1) * 48;         // 2 warps in N, 48 cols each
    int mBase = blockIdx.y * 128;
    int nBase = blockIdx.x * 96;

    const bf16* Abase = A  + (size_t)mBase * K;
    const bf16* Bbase = Wt + (size_t)nBase * K;

    int lr  = tid >> 2;        // 0..31
    int lc8 = tid & 3;         // 16B chunk within 32-wide k

    auto loadTiles = [&](int kt, int s){
        bf16* as = AsB + s*128*LDA;
        bf16* bs = BsB + s*96*LDA;
        #pragma unroll
        for (int i = 0; i < 4; i++) {
            int r = lr + i*32;
            cpa16(&as[r*LDA + lc8*8], Abase + (size_t)r*K + kt + lc8*8);
        }
        #pragma unroll
        for (int i = 0; i < 3; i++) {
            int r = lr + i*32;
            cpa16(&bs[r*LDA + lc8*8], Bbase + (size_t)r*K + kt + lc8*8);
        }
        asm volatile("cp.async.commit_group;" ::: "memory");
    };

    float acc[4][6][4];
    #pragma unroll
    for (int mi=0;mi<4;mi++)
        #pragma unroll
        for (int ni=0;ni<6;ni++)
            #pragma unroll
            for (int c=0;c<4;c++) acc[mi][ni][c] = 0.f;

    int aRowOff = ((lane>>3)&1)*8 + (lane&7);
    int aColOff = ((lane>>4)&1)*8;
    int bRowOff = ((lane>>4)&1)*8 + (lane&7);
    int bColOff = ((lane>>3)&1)*8;

    // preload 3 stages
    loadTiles(0,  0);
    loadTiles(32, 1);
    loadTiles(64, 2);

    #pragma unroll
    for (int it = 0; it < NITER; it++) {
        int rem = NITER - 1 - it;
        if (rem >= 2)      asm volatile("cp.async.wait_group 2;" ::: "memory");
        else if (rem == 1) asm volatile("cp.async.wait_group 1;" ::: "memory");
        else               asm volatile("cp.async.wait_group 0;" ::: "memory");
        // Single barrier per iter: also proves every warp finished iter it-1,
        // so overwriting stage (it+3)%4 (last read in iter it-1) is safe.
        __syncthreads();
        if (it + 3 < NITER) loadTiles((it+3)*32, (it+3)%NSTG);

        const bf16* as = AsB + (it%NSTG)*128*LDA;
        const bf16* bs = BsB + (it%NSTG)*96*LDA;

        uint32_t af[2][4][4], bfr[2][3][4];
        #pragma unroll
        for (int ks = 0; ks < 2; ks++) {
            #pragma unroll
            for (int mi = 0; mi < 4; mi++)
                ldm4(af[ks][mi], &as[(wm + mi*16 + aRowOff)*LDA + ks*16 + aColOff]);
            #pragma unroll
            for (int p = 0; p < 3; p++)
                ldm4(bfr[ks][p], &bs[(wn + p*16 + bRowOff)*LDA + ks*16 + bColOff]);
        }
        #pragma unroll
        for (int ks = 0; ks < 2; ks++)
            #pragma unroll
            for (int mi = 0; mi < 4; mi++)
                #pragma unroll
                for (int p = 0; p < 3; p++) {
                    mma_bf16(acc[mi][2*p  ], af[ks][mi][0], af[ks][mi][1], af[ks][mi][2], af[ks][mi][3],
                             bfr[ks][p][0], bfr[ks][p][1]);
                    mma_bf16(acc[mi][2*p+1], af[ks][mi][0], af[ks][mi][1], af[ks][mi][2], af[ks][mi][3],
                             bfr[ks][p][2], bfr[ks][p][3]);
                }
    }

    // ---------------- epilogue ----------------
    #pragma unroll
    for (int ni = 0; ni < 6; ni++) {
        int n = nBase + wn + ni*8 + t4*2;
        float b0v = __ldg(bias + n), b1v = __ldg(bias + n + 1);
        #pragma unroll
        for (int mi = 0; mi < 4; mi++) {
            #pragma unroll
            for (int h = 0; h < 2; h++) {
                int m = mBase + wm + mi*16 + h*8 + g;
                float u0 = acc[mi][ni][h*2+0] + b0v;
                float u1 = acc[mi][ni][h*2+1] + b1v;
                if (EPI == 1) {
                    float y0 = 0.7978845608028654f * (u0 + 0.044715f*u0*u0*u0);
                    float y1 = 0.7978845608028654f * (u1 + 0.044715f*u1*u1*u1);
                    float t0 = 1.f - 2.f/(__expf(2.f*y0)+1.f);
                    float t1 = 1.f - 2.f/(__expf(2.f*y1)+1.f);
                    u0 = 0.5f*u0*(1.f+t0);
                    u1 = 0.5f*u1*(1.f+t1);
                }
                if (EPI == 0 || EPI == 1) {
                    *(uint32_t*)((bf16*)outp + (size_t)m * N + n) = packbf2(u0, u1);
                } else {
                    size_t drow = (EPI == 2) ? winrow_to_img(m) : (size_t)m;
                    size_t o = drow * CC + n;
                    float2 xv = *(const float2*)(xin + o);
                    float2 ov; ov.x = u0 + xv.x; ov.y = u1 + xv.y;
                    *(float2*)((float*)outp + o) = ov;
                }
            }
        }
    }
}

// ---------------- HMMA windowed attention: one block per (window, head) ----------------
// Q/K staged via 16B cp.async (scale folded into post-MMA); V scalar-transposed.
#define ALD 40
#define VLD 72

__global__ __launch_bounds__(128) void attn_mma(const bf16* __restrict__ qkv,
                                                const float* __restrict__ btab,
                                                bf16* __restrict__ out)
{
    __shared__ __align__(16) bf16 sq[64*ALD];
    __shared__ __align__(16) bf16 sk[64*ALD];
    __shared__ __align__(16) bf16 sVt[32*VLD];
    __shared__ __align__(16) float sbias[64*64];

    int win  = blockIdx.x / NHH;
    int head = blockIdx.x % NHH;
    int tid  = threadIdx.x;
    int lane = tid & 31, w = tid >> 5;
    int g = lane >> 2, t4 = lane & 3;

    int wi = win & 63;
    int wtype = (((wi>>3) == 7) ? 2 : 0) + (((wi&7) == 7) ? 1 : 0);
    const float* bt = btab + ((size_t)(wtype*NHH + head))*4096;
    #pragma unroll
    for (int i = 0; i < 8; i++)
        cpa16(&sbias[(tid + i*128)*4], bt + (tid + i*128)*4);
    asm volatile("cp.async.commit_group;" ::: "memory");

    // zero-fill q/k rows + full sVt (padding correctness)
    uint32_t* zq = (uint32_t*)sq;
    uint32_t* zk = (uint32_t*)sk;
    uint32_t* zv = (uint32_t*)sVt;
    #pragma unroll
    for (int i = 0; i < 10; i++) { zq[tid + i*128] = 0u; zk[tid + i*128] = 0u; }
    #pragma unroll
    for (int i = 0; i < 9; i++)  { zv[tid + i*128] = 0u; }
    __syncthreads();   // zeros visible before cp.async / scalar overwrite

    const bf16* base = qkv + (size_t)win*NN*(3*CC) + head*HD;
    // Q,K: 49 rows x 4 x16B chunks each, coalesced cp.async
    for (int i = tid; i < 196; i += 128) {
        int n = i >> 2, c = i & 3;
        cpa16(&sq[n*ALD + c*8], base + (size_t)n*(3*CC) + c*8);
        cpa16(&sk[n*ALD + c*8], base + (size_t)n*(3*CC) + CC + c*8);
    }
    asm volatile("cp.async.commit_group;" ::: "memory");
    // V: scalar transpose into sVt[d][n]
    for (int i = tid; i < NN*HD; i += 128) {
        int n = i >> 5, d = i & 31;
        sVt[d*VLD + n] = base[(size_t)n*(3*CC) + 2*CC + d];
    }
    asm volatile("cp.async.wait_group 0;" ::: "memory");
    __syncthreads();

    float sa[8][4];
    #pragma unroll
    for (int nt = 0; nt < 8; nt++)
        #pragma unroll
        for (int c = 0; c < 4; c++) sa[nt][c] = 0.f;

    int r0 = w*16 + g;
    #pragma unroll
    for (int kt = 0; kt < 2; kt++) {
        uint32_t a0 = *(const uint32_t*)&sq[(r0  )*ALD + kt*16 + t4*2    ];
        uint32_t a1 = *(const uint32_t*)&sq[(r0+8)*ALD + kt*16 + t4*2    ];
        uint32_t a2 = *(const uint32_t*)&sq[(r0  )*ALD + kt*16 + t4*2 + 8];
        uint32_t a3 = *(const uint32_t*)&sq[(r0+8)*ALD + kt*16 + t4*2 + 8];
        #pragma unroll
        for (int nt = 0; nt < 8; nt++) {
            int n0 = nt*8 + g;
            uint32_t b0 = *(const uint32_t*)&sk[n0*ALD + kt*16 + t4*2    ];
            uint32_t b1 = *(const uint32_t*)&sk[n0*ALD + kt*16 + t4*2 + 8];
            mma_bf16(sa[nt], a0, a1, a2, a3, b0, b1);
        }
    }

    // softmax (scale folded here: sa*scale + bias)
    const float scale = 0.17677669529663687f;
    int rlo = r0, rhi = r0 + 8;
    float mlo = -1e30f, mhi = -1e30f;
    #pragma unroll
    for (int nt = 0; nt < 8; nt++) {
        float2 blo = *(const float2*)&sbias[rlo*64 + nt*8 + t4*2];
        float2 bhi = *(const float2*)&sbias[rhi*64 + nt*8 + t4*2];
        sa[nt][0] = fmaf(sa[nt][0], scale, blo.x);
        sa[nt][1] = fmaf(sa[nt][1], scale, blo.y);
        sa[nt][2] = fmaf(sa[nt][2], scale, bhi.x);
        sa[nt][3] = fmaf(sa[nt][3], scale, bhi.y);
        mlo = fmaxf(mlo, fmaxf(sa[nt][0], sa[nt][1]));
        mhi = fmaxf(mhi, fmaxf(sa[nt][2], sa[nt][3]));
    }
    mlo = fmaxf(mlo, __shfl_xor_sync(0xffffffffu, mlo, 1));
    mlo = fmaxf(mlo, __shfl_xor_sync(0xffffffffu, mlo, 2));
    mhi = fmaxf(mhi, __shfl_xor_sync(0xffffffffu, mhi, 1));
    mhi = fmaxf(mhi, __shfl_xor_sync(0xffffffffu, mhi, 2));
    float slo = 0.f, shi = 0.f;
    #pragma unroll
    for (int nt = 0; nt < 8; nt++) {
        sa[nt][0] = __expf(sa[nt][0] - mlo);
        sa[nt][1] = __expf(sa[nt][1] - mlo);
        sa[nt][2] = __expf(sa[nt][2] - mhi);
        sa[nt][3] = __expf(sa[nt][3] - mhi);
        slo += sa[nt][0] + sa[nt][1];
        shi += sa[nt][2] + sa[nt][3];
    }
    slo += __shfl_xor_sync(0xffffffffu, slo, 1);
    slo += __shfl_xor_sync(0xffffffffu, slo, 2);
    shi += __shfl_xor_sync(0xffffffffu, shi, 1);
    shi += __shfl_xor_sync(0xffffffffu, shi, 2);
    float ilo = 1.f / slo, ihi = 1.f / shi;

    uint32_t plo[8], phi[8];
    #pragma unroll
    for (int nt = 0; nt < 8; nt++) {
        plo[nt] = packbf2(sa[nt][0]*ilo, sa[nt][1]*ilo);
        phi[nt] = packbf2(sa[nt][2]*ihi, sa[nt][3]*ihi);
    }

    float oacc[4][4];
    #pragma unroll
    for (int nt = 0; nt < 4; nt++)
        #pragma unroll
        for (int c = 0; c < 4; c++) oacc[nt][c] = 0.f;

    #pragma unroll
    for (int kt = 0; kt < 4; kt++) {
        uint32_t a0 = plo[2*kt], a1 = phi[2*kt], a2 = plo[2*kt+1], a3 = phi[2*kt+1];
        #pragma unroll
        for (int nt = 0; nt < 4; nt++) {
            int n0 = nt*8 + g;
            uint32_t b0 = *(const uint32_t*)&sVt[n0*VLD + kt*16 + t4*2    ];
            uint32_t b1 = *(const uint32_t*)&sVt[n0*VLD + kt*16 + t4*2 + 8];
            mma_bf16(oacc[nt], a0, a1, a2, a3, b0, b1);
        }
    }

    #pragma unroll
    for (int nt = 0; nt < 4; nt++) {
        int col = nt*8 + t4*2;
        if (rlo < NN)
            *(uint32_t*)(out + ((size_t)(win*NN + rlo))*CC + head*HD + col) =
                packbf2(oacc[nt][0], oacc[nt][1]);
        if (rhi < NN)
            *(uint32_t*)(out + ((size_t)(win*NN + rhi))*CC + head*HD + col) =
                packbf2(oacc[nt][2], oacc[nt][3]);
    }
}

// ---------------- launch ----------------
extern "C" void kernel_launch(void* const* d_in, const int* in_sizes, int n_in,
                              void* d_out, int out_size)
{
    const float* x      = (const float*)d_in[0];
    const float* qkv_w  = (const float*)d_in[1];
    const float* qkv_b  = (const float*)d_in[2];
    const float* proj_w = (const float*)d_in[3];
    const float* proj_b = (const float*)d_in[4];
    const float* rpb    = (const float*)d_in[5];
    const float* n1g    = (const float*)d_in[6];
    const float* n1b    = (const float*)d_in[7];
    const float* n2g    = (const float*)d_in[8];
    const float* n2b    = (const float*)d_in[9];
    const float* w1     = (const float*)d_in[10];
    const float* b1     = (const float*)d_in[11];
    const float* w2     = (const float*)d_in[12];
    const float* b2     = (const float*)d_in[13];
    float* out = (float*)d_out;

    bf16 *p_ln1, *p_qkvb, *p_attnb, *p_ln2, *p_h1b, *p_wq, *p_wp, *p_w1, *p_w2;
    float *p_x1, *p_bias;
    cudaGetSymbolAddress((void**)&p_ln1,  g_ln1);
    cudaGetSymbolAddress((void**)&p_qkvb, g_qkvb);
    cudaGetSymbolAddress((void**)&p_attnb,g_attnb);
    cudaGetSymbolAddress((void**)&p_ln2,  g_ln2);
    cudaGetSymbolAddress((void**)&p_h1b,  g_h1b);
    cudaGetSymbolAddress((void**)&p_x1,   g_x1);
    cudaGetSymbolAddress((void**)&p_wq,   g_wq);
    cudaGetSymbolAddress((void**)&p_wp,   g_wp);
    cudaGetSymbolAddress((void**)&p_w1,   g_w1);
    cudaGetSymbolAddress((void**)&p_w2,   g_w2);
    cudaGetSymbolAddress((void**)&p_bias, g_bias);

    cudaFuncSetAttribute(mma_gemm<0, 3*CC, CC>, cudaFuncAttributeMaxDynamicSharedMemorySize, GEMM_SMEM);
    cudaFuncSetAttribute(mma_gemm<2, CC, CC>,   cudaFuncAttributeMaxDynamicSharedMemorySize, GEMM_SMEM);
    cudaFuncSetAttribute(mma_gemm<1, HID, CC>,  cudaFuncAttributeMaxDynamicSharedMemorySize, GEMM_SMEM);
    cudaFuncSetAttribute(mma_gemm<3, CC, HID>,  cudaFuncAttributeMaxDynamicSharedMemorySize, GEMM_SMEM);

    // 0) weights -> bf16 + bias tables
    f2bf4_kernel<<<(S3 + 255)/256, 256>>>(qkv_w, proj_w, w1, w2, p_wq, p_wp, p_w1, p_w2);
    bias_pre_kernel<<<4*NHH, 256>>>(rpb, p_bias);

    // 1) LN1 + roll + window partition -> bf16
    ln_kernel<true><<<TOK/8, 256>>>(x, n1g, n1b, p_ln1);

    // 2) qkv GEMM
    mma_gemm<0, 3*CC, CC><<<dim3(6, TOK/128), 128, GEMM_SMEM>>>(p_ln1, p_wq, qkv_b, nullptr, p_qkvb);

    // 3) windowed attention (HMMA)
    attn_mma<<<BW*NHH, 128>>>(p_qkvb, p_bias, p_attnb);

    // 4) proj GEMM + window reverse + residual -> g_x1 (fp32)
    mma_gemm<2, CC, CC><<<dim3(2, TOK/128), 128, GEMM_SMEM>>>(p_attnb, p_wp, proj_b, x, p_x1);

    // 5) LN2 -> bf16
    ln_kernel<false><<<TOK/8, 256>>>(p_x1, n2g, n2b, p_ln2);

    // 6) fc1 + gelu -> bf16
    mma_gemm<1, HID, CC><<<dim3(8, TOK/128), 128, GEMM_SMEM>>>(p_ln2, p_w1, b1, nullptr, p_h1b);

    // 7) fc2 + bias + residual -> d_out (fp32)
    mma_gemm<3, CC, HID><<<dim3(2, TOK/128), 128, GEMM_SMEM>>>(p_h1b, p_w2, b2, p_x1, out);
}